// round 7
// baseline (speedup 1.0000x reference)
#include <cuda_runtime.h>

// Problem constants (fixed shapes per reference)
#define NSUM 6400
#define NMAX 64
#define MDIM 16
#define HDIM 32
#define ODIM 32
#define EDGES 51200

// Scratch: ping/pong node-feature buffers + CSR structures + pool partials.
__device__ float g_h[2][NSUM * NMAX * HDIM];   // 2 x 52.4 MB
__device__ float g_pool[NSUM * 2 * 32];        // per-half pool partials
__device__ int g_cnt[NSUM];                    // zero-init at load; k_scan re-zeroes
__device__ int g_off[NSUM + 1];
__device__ int g_cur[NSUM];
__device__ int g_esrc[EDGES];

// ---------------------------------------------------------------------------
// CSR build: count -> scan (self-cleaning) -> scatter
// ---------------------------------------------------------------------------
__global__ void k_count(const int* __restrict__ dst) {
    int e = blockIdx.x * blockDim.x + threadIdx.x;
    if (e < EDGES) atomicAdd(&g_cnt[dst[e]], 1);
}

__global__ void k_scan() {
    __shared__ int part[1024];
    int tid = threadIdx.x;
    const int CH = (NSUM + 1023) / 1024;  // 7
    int base = tid * CH;
    int s = 0;
    #pragma unroll
    for (int i = 0; i < CH; i++) {
        int idx = base + i;
        if (idx < NSUM) s += g_cnt[idx];
    }
    part[tid] = s;
    __syncthreads();
    int own = s;
    for (int d = 1; d < 1024; d <<= 1) {
        int v = (tid >= d) ? part[tid - d] : 0;
        __syncthreads();
        part[tid] += v;
        __syncthreads();
    }
    int run = part[tid] - own;
    #pragma unroll
    for (int i = 0; i < CH; i++) {
        int idx = base + i;
        if (idx < NSUM) {
            g_off[idx] = run;
            g_cur[idx] = run;
            run += g_cnt[idx];
            g_cnt[idx] = 0;          // self-clean for the next replay
        }
    }
    if (tid == 1023) g_off[NSUM] = EDGES;
}

__global__ void k_scatter(const int* __restrict__ src, const int* __restrict__ dst) {
    int e = blockIdx.x * blockDim.x + threadIdx.x;
    if (e < EDGES) {
        int p = atomicAdd(&g_cur[dst[e]], 1);
        g_esrc[p] = src[e];
    }
}

// ---------------------------------------------------------------------------
// Warp-autonomous fused GIN layer.
// Unit = (node, half of 32 rows). One warp per unit; grid-stride over units.
// Lane (lr = lane>>2, q = lane&3) owns 4 rows {lr, lr+8, lr+16, lr+24} of
// its half, and 8 output columns [q*8, q*8+8).
//   occupancy: 3 blocks/SM (24 warps) via __launch_bounds__(256,3); gather
//              latency of one warp hides under other warps' FFMA streams.
//   gather : edge ids broadcast via shfl; edge-unroll 2 for D=16 (register
//            budget allows double buffering), 1 for D=32 (8 LDG in flight).
//   MLP    : LDS.128 reads with broadcast dedup; hid overwrites x (union).
//   pool   : local 4-row sum + shfl over lr bits; 2 partials/node + reduce
// ---------------------------------------------------------------------------
template <int DIN, bool RELU_OUT, bool POOL>
__global__ __launch_bounds__(256, 3) void k_layer(
    const float* __restrict__ ext_in, int in_buf, int out_buf,
    const float* __restrict__ epsv, int layer,
    const float* __restrict__ W1, const float* __restrict__ b1,
    const float* __restrict__ W2, const float* __restrict__ b2)
{
    constexpr int R4   = DIN / 4;          // float4 per row
    constexpr int PFR  = R4 / 4;           // float4 per lane per row (1 or 2)
    constexpr int S    = 4 * PFR;          // float4 slots per lane (4 or 8)
    constexpr int V4   = NMAX * R4;        // float4 per node block
    constexpr int PAD  = 36;               // row stride (floats); 144B = 16B-aligned
    constexpr bool EU2 = (S <= 4);         // 2-edge unroll only when regs allow

    __shared__ float sW1[DIN * 32];
    __shared__ float sW2[32 * 32];
    __shared__ float sb1[32], sb2[32];
    __shared__ float sxh[8][32 * PAD];     // per-warp x/hid union slices

    int tid = threadIdx.x;
    int wid = tid >> 5, lane = tid & 31;
    int lr = lane >> 2, q = lane & 3;

    for (int i = tid; i < DIN * 32; i += 256) sW1[i] = W1[i];
    for (int i = tid; i < 32 * 32;  i += 256) sW2[i] = W2[i];
    if (tid < 32) { sb1[tid] = b1[tid]; sb2[tid] = b2[tid]; }
    float ep1 = 1.0f + epsv[layer];
    __syncthreads();

    const float*  h_in = ext_in ? ext_in : g_h[in_buf];
    const float4* h4   = (const float4*)h_in;
    float* sxw = sxh[wid];

    for (int unit = blockIdx.x * 8 + wid; unit < NSUM * 2; unit += gridDim.x * 8) {
        int n = unit >> 1, half = unit & 1;
        // lane's float4 slots within the node block (4 rows x PFR slices)
        int slot[S];
        #pragma unroll
        for (int m = 0; m < 4; m++)
            #pragma unroll
            for (int v = 0; v < PFR; v++)
                slot[m * PFR + v] = (half * 32 + lr + 8 * m) * R4 + q + 4 * v;

        // ---- gather: acc = (1+eps)*h[n] + sum_neighbors h[src] ----
        float4 acc[S];
        {
            const float4* hn = h4 + (size_t)n * V4;
            #pragma unroll
            for (int s = 0; s < S; s++) {
                float4 t = hn[slot[s]];
                acc[s] = make_float4(ep1 * t.x, ep1 * t.y, ep1 * t.z, ep1 * t.w);
            }
        }
        int e0 = g_off[n], e1 = g_off[n + 1];
        for (int base = e0; base < e1; base += 32) {
            int cnt = min(32, e1 - base);
            int id = (lane < cnt) ? g_esrc[base + lane] : 0;
            int e = 0;
            if (EU2) {
                for (; e + 2 <= cnt; e += 2) {
                    int sa = __shfl_sync(0xffffffffu, id, e);
                    int sb = __shfl_sync(0xffffffffu, id, e + 1);
                    const float4* pa = h4 + (size_t)sa * V4;
                    const float4* pb = h4 + (size_t)sb * V4;
                    float4 ta[S], tb[S];
                    #pragma unroll
                    for (int s = 0; s < S; s++) ta[s] = pa[slot[s]];
                    #pragma unroll
                    for (int s = 0; s < S; s++) tb[s] = pb[slot[s]];
                    #pragma unroll
                    for (int s = 0; s < S; s++) {
                        acc[s].x += ta[s].x; acc[s].y += ta[s].y;
                        acc[s].z += ta[s].z; acc[s].w += ta[s].w;
                    }
                    #pragma unroll
                    for (int s = 0; s < S; s++) {
                        acc[s].x += tb[s].x; acc[s].y += tb[s].y;
                        acc[s].z += tb[s].z; acc[s].w += tb[s].w;
                    }
                }
            }
            for (; e < cnt; e++) {
                int sa = __shfl_sync(0xffffffffu, id, e);
                const float4* pa = h4 + (size_t)sa * V4;
                float4 t[S];
                #pragma unroll
                for (int s = 0; s < S; s++) t[s] = pa[slot[s]];
                #pragma unroll
                for (int s = 0; s < S; s++) {
                    acc[s].x += t[s].x; acc[s].y += t[s].y;
                    acc[s].z += t[s].z; acc[s].w += t[s].w;
                }
            }
        }
        // stage x into this warp's smem slice (local rows lr+8m)
        #pragma unroll
        for (int m = 0; m < 4; m++)
            #pragma unroll
            for (int v = 0; v < PFR; v++) {
                float* p = &sxw[(lr + 8 * m) * PAD + 4 * q + 16 * v];
                *(float4*)p = acc[m * PFR + v];
            }
        __syncwarp();

        // ---- hidden: hid = relu(x @ W1 + b1); lane: 4 rows x 8 cols ----
        float hacc[32];
        #pragma unroll
        for (int m = 0; m < 4; m++)
            #pragma unroll
            for (int i = 0; i < 8; i++) hacc[m * 8 + i] = sb1[q * 8 + i];
        #pragma unroll
        for (int kb = 0; kb < DIN / 4; kb++) {
            float4 xq0 = *(const float4*)&sxw[(lr +  0) * PAD + kb * 4];
            float4 xq1 = *(const float4*)&sxw[(lr +  8) * PAD + kb * 4];
            float4 xq2 = *(const float4*)&sxw[(lr + 16) * PAD + kb * 4];
            float4 xq3 = *(const float4*)&sxw[(lr + 24) * PAD + kb * 4];
            float x0[4] = {xq0.x, xq0.y, xq0.z, xq0.w};
            float x1[4] = {xq1.x, xq1.y, xq1.z, xq1.w};
            float x2[4] = {xq2.x, xq2.y, xq2.z, xq2.w};
            float x3[4] = {xq3.x, xq3.y, xq3.z, xq3.w};
            #pragma unroll
            for (int kk = 0; kk < 4; kk++) {
                int k = kb * 4 + kk;
                float4 w0 = *(const float4*)&sW1[k * 32 + q * 8];
                float4 w1 = *(const float4*)&sW1[k * 32 + q * 8 + 4];
                float w[8] = {w0.x, w0.y, w0.z, w0.w, w1.x, w1.y, w1.z, w1.w};
                #pragma unroll
                for (int i = 0; i < 8; i++) {
                    hacc[ 0 + i] = fmaf(x0[kk], w[i], hacc[ 0 + i]);
                    hacc[ 8 + i] = fmaf(x1[kk], w[i], hacc[ 8 + i]);
                    hacc[16 + i] = fmaf(x2[kk], w[i], hacc[16 + i]);
                    hacc[24 + i] = fmaf(x3[kk], w[i], hacc[24 + i]);
                }
            }
        }
        __syncwarp();   // all x reads done before hid overwrites the buffer
        #pragma unroll
        for (int m = 0; m < 4; m++) {
            float* p = &sxw[(lr + 8 * m) * PAD + q * 8];
            ((float4*)p)[0] = make_float4(fmaxf(hacc[m*8+0], 0.f), fmaxf(hacc[m*8+1], 0.f),
                                          fmaxf(hacc[m*8+2], 0.f), fmaxf(hacc[m*8+3], 0.f));
            ((float4*)p)[1] = make_float4(fmaxf(hacc[m*8+4], 0.f), fmaxf(hacc[m*8+5], 0.f),
                                          fmaxf(hacc[m*8+6], 0.f), fmaxf(hacc[m*8+7], 0.f));
        }
        __syncwarp();

        // ---- output: out = hid @ W2 + b2 ----
        float oacc[32];
        #pragma unroll
        for (int m = 0; m < 4; m++)
            #pragma unroll
            for (int i = 0; i < 8; i++) oacc[m * 8 + i] = sb2[q * 8 + i];
        #pragma unroll
        for (int jb = 0; jb < 8; jb++) {
            float4 hq0 = *(const float4*)&sxw[(lr +  0) * PAD + jb * 4];
            float4 hq1 = *(const float4*)&sxw[(lr +  8) * PAD + jb * 4];
            float4 hq2 = *(const float4*)&sxw[(lr + 16) * PAD + jb * 4];
            float4 hq3 = *(const float4*)&sxw[(lr + 24) * PAD + jb * 4];
            float h0[4] = {hq0.x, hq0.y, hq0.z, hq0.w};
            float h1[4] = {hq1.x, hq1.y, hq1.z, hq1.w};
            float h2[4] = {hq2.x, hq2.y, hq2.z, hq2.w};
            float h3[4] = {hq3.x, hq3.y, hq3.z, hq3.w};
            #pragma unroll
            for (int jj = 0; jj < 4; jj++) {
                int j = jb * 4 + jj;
                float4 w0 = *(const float4*)&sW2[j * 32 + q * 8];
                float4 w1 = *(const float4*)&sW2[j * 32 + q * 8 + 4];
                float w[8] = {w0.x, w0.y, w0.z, w0.w, w1.x, w1.y, w1.z, w1.w};
                #pragma unroll
                for (int i = 0; i < 8; i++) {
                    oacc[ 0 + i] = fmaf(h0[jj], w[i], oacc[ 0 + i]);
                    oacc[ 8 + i] = fmaf(h1[jj], w[i], oacc[ 8 + i]);
                    oacc[16 + i] = fmaf(h2[jj], w[i], oacc[16 + i]);
                    oacc[24 + i] = fmaf(h3[jj], w[i], oacc[24 + i]);
                }
            }
        }
        __syncwarp();   // hid reads done before next iteration stages x

        if (!POOL) {
            #pragma unroll
            for (int m = 0; m < 4; m++) {
                int grow = half * 32 + lr + 8 * m;
                float* out = g_h[out_buf] + (size_t)n * (NMAX * 32) + grow * 32 + q * 8;
                float4 o0 = make_float4(oacc[m*8+0], oacc[m*8+1], oacc[m*8+2], oacc[m*8+3]);
                float4 o1 = make_float4(oacc[m*8+4], oacc[m*8+5], oacc[m*8+6], oacc[m*8+7]);
                if (RELU_OUT) {
                    o0.x = fmaxf(o0.x, 0.f); o0.y = fmaxf(o0.y, 0.f);
                    o0.z = fmaxf(o0.z, 0.f); o0.w = fmaxf(o0.w, 0.f);
                    o1.x = fmaxf(o1.x, 0.f); o1.y = fmaxf(o1.y, 0.f);
                    o1.z = fmaxf(o1.z, 0.f); o1.w = fmaxf(o1.w, 0.f);
                }
                ((float4*)out)[0] = o0;
                ((float4*)out)[1] = o1;
            }
        } else {
            // local sum over this lane's 4 rows
            float o[8];
            #pragma unroll
            for (int i = 0; i < 8; i++)
                o[i] = oacc[i] + oacc[8 + i] + oacc[16 + i] + oacc[24 + i];
            // reduce over lr (lane bits 2..4)
            #pragma unroll
            for (int s = 4; s <= 16; s <<= 1) {
                #pragma unroll
                for (int i = 0; i < 8; i++)
                    o[i] += __shfl_xor_sync(0xffffffffu, o[i], s);
            }
            if (lane < 4) {
                float* p = &g_pool[n * 64 + half * 32 + q * 8];
                ((float4*)p)[0] = make_float4(o[0], o[1], o[2], o[3]);
                ((float4*)p)[1] = make_float4(o[4], o[5], o[6], o[7]);
            }
        }
    }
}

// Reduce the 2 per-half partials into the final [NSUM, 32] output.
__global__ void k_pool_reduce(float* __restrict__ dout) {
    int i = blockIdx.x * blockDim.x + threadIdx.x;   // i = n*32 + c
    if (i < NSUM * 32) {
        int n = i >> 5, c = i & 31;
        dout[i] = g_pool[n * 64 + c] + g_pool[n * 64 + 32 + c];
    }
}

// ---------------------------------------------------------------------------
extern "C" void kernel_launch(void* const* d_in, const int* in_sizes, int n_in,
                              void* d_out, int out_size)
{
    const float* W    = (const float*)d_in[0];   // [6400, 64, 16]
    const int*   ei   = (const int*)d_in[1];     // [2, E] row-major
    const float* eps  = (const float*)d_in[2];   // [3]
    const float* W1_0 = (const float*)d_in[3];
    const float* b1_0 = (const float*)d_in[4];
    const float* W2_0 = (const float*)d_in[5];
    const float* b2_0 = (const float*)d_in[6];
    const float* W1_1 = (const float*)d_in[7];
    const float* b1_1 = (const float*)d_in[8];
    const float* W2_1 = (const float*)d_in[9];
    const float* b2_1 = (const float*)d_in[10];
    const float* W1_2 = (const float*)d_in[11];
    const float* b1_2 = (const float*)d_in[12];
    const float* W2_2 = (const float*)d_in[13];
    const float* b2_2 = (const float*)d_in[14];
    float* out = (float*)d_out;

    const int* src = ei;
    const int* dst = ei + EDGES;

    // CSR build (g_cnt is zero at load and re-zeroed by k_scan each call)
    k_count<<<(EDGES + 255) / 256, 256>>>(dst);          // launch 0
    k_scan<<<1, 1024>>>();                                // launch 1
    k_scatter<<<(EDGES + 255) / 256, 256>>>(src, dst);   // launch 2

    const int GRID = 444;   // one persistent wave: 3 blocks x 148 SMs

    // Layer 0: input W (D=16) -> g_h[0]  (relu after MLP)   -- launch 3
    k_layer<16, true, false><<<GRID, 256>>>(W, 0, 0, eps, 0,
                                            W1_0, b1_0, W2_0, b2_0);
    // Layer 1: g_h[0] -> g_h[1]  (relu after MLP)           -- launch 4
    k_layer<32, true, false><<<GRID, 256>>>(nullptr, 0, 1, eps, 1,
                                            W1_1, b1_1, W2_1, b2_1);
    // Layer 2: g_h[1] -> per-half pool partials (no relu)   -- launch 5
    k_layer<32, false, true><<<GRID, 256>>>(nullptr, 1, 0, eps, 2,
                                            W1_2, b1_2, W2_2, b2_2);
    // Final: reduce 2 half partials per node                -- launch 6
    k_pool_reduce<<<(NSUM * 32 + 255) / 256, 256>>>(out);
}

// round 9
// speedup vs baseline: 1.0526x; 1.0526x over previous
#include <cuda_runtime.h>

// Problem constants (fixed shapes per reference)
#define NSUM 6400
#define NMAX 64
#define MDIM 16
#define HDIM 32
#define ODIM 32
#define EDGES 51200

// Scratch: ping/pong node-feature buffers + CSR structures + pool partials.
__device__ float g_h[2][NSUM * NMAX * HDIM];   // 2 x 52.4 MB
__device__ float g_pool[NSUM * 2 * 32];        // per-half pool partials
__device__ int g_cnt[NSUM];                    // zero-init at load; k_scan re-zeroes
__device__ int g_off[NSUM + 1];
__device__ int g_cur[NSUM];
__device__ int g_esrc[EDGES];

// ---- packed fp32x2 helpers (Blackwell dual-FMA; full fp32 precision) ----
__device__ __forceinline__ unsigned long long pack2(float lo, float hi) {
    unsigned long long r;
    asm("mov.b64 %0, {%1, %2};" : "=l"(r) : "f"(lo), "f"(hi));
    return r;
}
__device__ __forceinline__ unsigned long long pack2dup(float v) {
    unsigned long long r;
    asm("mov.b64 %0, {%1, %1};" : "=l"(r) : "f"(v));
    return r;
}
__device__ __forceinline__ void fma2(unsigned long long& d,
                                     unsigned long long a, unsigned long long b) {
    asm("fma.rn.f32x2 %0, %1, %2, %0;" : "+l"(d) : "l"(a), "l"(b));
}
__device__ __forceinline__ float2 unpack2(unsigned long long v) {
    float lo, hi;
    asm("mov.b64 {%0, %1}, %2;" : "=f"(lo), "=f"(hi) : "l"(v));
    return make_float2(lo, hi);
}

// ---------------------------------------------------------------------------
// CSR build: count -> scan (self-cleaning) -> scatter
// ---------------------------------------------------------------------------
__global__ void k_count(const int* __restrict__ dst) {
    int e = blockIdx.x * blockDim.x + threadIdx.x;
    if (e < EDGES) atomicAdd(&g_cnt[dst[e]], 1);
}

__global__ void k_scan() {
    __shared__ int part[1024];
    int tid = threadIdx.x;
    const int CH = (NSUM + 1023) / 1024;  // 7
    int base = tid * CH;
    int s = 0;
    #pragma unroll
    for (int i = 0; i < CH; i++) {
        int idx = base + i;
        if (idx < NSUM) s += g_cnt[idx];
    }
    part[tid] = s;
    __syncthreads();
    int own = s;
    for (int d = 1; d < 1024; d <<= 1) {
        int v = (tid >= d) ? part[tid - d] : 0;
        __syncthreads();
        part[tid] += v;
        __syncthreads();
    }
    int run = part[tid] - own;
    #pragma unroll
    for (int i = 0; i < CH; i++) {
        int idx = base + i;
        if (idx < NSUM) {
            g_off[idx] = run;
            g_cur[idx] = run;
            run += g_cnt[idx];
            g_cnt[idx] = 0;          // self-clean for the next replay
        }
    }
    if (tid == 1023) g_off[NSUM] = EDGES;
}

__global__ void k_scatter(const int* __restrict__ src, const int* __restrict__ dst) {
    int e = blockIdx.x * blockDim.x + threadIdx.x;
    if (e < EDGES) {
        int p = atomicAdd(&g_cur[dst[e]], 1);
        g_esrc[p] = src[e];
    }
}

// ---------------------------------------------------------------------------
// Warp-autonomous fused GIN layer with packed f32x2 dual-FMA MLP.
// Unit = (node, half of 32 rows). One warp per unit; grid-stride over units.
// Lane (lr = lane>>2, q = lane&3) owns 4 rows {lr, lr+8, lr+16, lr+24} of
// its half, and 8 output columns [q*8, q*8+8) held as 4 column-pairs.
//   gather : edge ids broadcast via shfl; 2-edge unroll for D=16 only
//   MLP    : per k-step 2 weight LDS.128 -> 4 col-pair operands; per row a
//            duplicated x pair; 16 fma.rn.f32x2 = 32 MACs. Full fp32.
//   pool   : local 4-row sum + shfl over lr bits; 2 partials/node + reduce
// ---------------------------------------------------------------------------
template <int DIN, bool RELU_OUT, bool POOL>
__global__ __launch_bounds__(256, 2) void k_layer(
    const float* __restrict__ ext_in, int in_buf, int out_buf,
    const float* __restrict__ epsv, int layer,
    const float* __restrict__ W1, const float* __restrict__ b1,
    const float* __restrict__ W2, const float* __restrict__ b2)
{
    constexpr int R4   = DIN / 4;          // float4 per row
    constexpr int PFR  = R4 / 4;           // float4 per lane per row (1 or 2)
    constexpr int S    = 4 * PFR;          // float4 slots per lane (4 or 8)
    constexpr int V4   = NMAX * R4;        // float4 per node block
    constexpr int PAD  = 36;               // row stride (floats); 144B = 16B-aligned
    constexpr bool EU2 = (S <= 4);         // 2-edge unroll only when regs allow

    __shared__ float sW1[DIN * 32];
    __shared__ float sW2[32 * 32];
    __shared__ float sb1[32], sb2[32];
    __shared__ float sxh[8][32 * PAD];     // per-warp x/hid union slices

    int tid = threadIdx.x;
    int wid = tid >> 5, lane = tid & 31;
    int lr = lane >> 2, q = lane & 3;

    for (int i = tid; i < DIN * 32; i += 256) sW1[i] = W1[i];
    for (int i = tid; i < 32 * 32;  i += 256) sW2[i] = W2[i];
    if (tid < 32) { sb1[tid] = b1[tid]; sb2[tid] = b2[tid]; }
    float ep1 = 1.0f + epsv[layer];
    __syncthreads();

    const float*  h_in = ext_in ? ext_in : g_h[in_buf];
    const float4* h4   = (const float4*)h_in;
    float* sxw = sxh[wid];

    for (int unit = blockIdx.x * 8 + wid; unit < NSUM * 2; unit += gridDim.x * 8) {
        int n = unit >> 1, half = unit & 1;
        // lane's float4 slots within the node block (4 rows x PFR slices)
        int slot[S];
        #pragma unroll
        for (int m = 0; m < 4; m++)
            #pragma unroll
            for (int v = 0; v < PFR; v++)
                slot[m * PFR + v] = (half * 32 + lr + 8 * m) * R4 + q + 4 * v;

        // ---- gather: acc = (1+eps)*h[n] + sum_neighbors h[src] ----
        float4 acc[S];
        {
            const float4* hn = h4 + (size_t)n * V4;
            #pragma unroll
            for (int s = 0; s < S; s++) {
                float4 t = hn[slot[s]];
                acc[s] = make_float4(ep1 * t.x, ep1 * t.y, ep1 * t.z, ep1 * t.w);
            }
        }
        int e0 = g_off[n], e1 = g_off[n + 1];
        for (int base = e0; base < e1; base += 32) {
            int cnt = min(32, e1 - base);
            int id = (lane < cnt) ? g_esrc[base + lane] : 0;
            int e = 0;
            if (EU2) {
                for (; e + 2 <= cnt; e += 2) {
                    int sa = __shfl_sync(0xffffffffu, id, e);
                    int sb = __shfl_sync(0xffffffffu, id, e + 1);
                    const float4* pa = h4 + (size_t)sa * V4;
                    const float4* pb = h4 + (size_t)sb * V4;
                    float4 ta[S], tb[S];
                    #pragma unroll
                    for (int s = 0; s < S; s++) ta[s] = pa[slot[s]];
                    #pragma unroll
                    for (int s = 0; s < S; s++) tb[s] = pb[slot[s]];
                    #pragma unroll
                    for (int s = 0; s < S; s++) {
                        acc[s].x += ta[s].x; acc[s].y += ta[s].y;
                        acc[s].z += ta[s].z; acc[s].w += ta[s].w;
                    }
                    #pragma unroll
                    for (int s = 0; s < S; s++) {
                        acc[s].x += tb[s].x; acc[s].y += tb[s].y;
                        acc[s].z += tb[s].z; acc[s].w += tb[s].w;
                    }
                }
            }
            for (; e < cnt; e++) {
                int sa = __shfl_sync(0xffffffffu, id, e);
                const float4* pa = h4 + (size_t)sa * V4;
                float4 t[S];
                #pragma unroll
                for (int s = 0; s < S; s++) t[s] = pa[slot[s]];
                #pragma unroll
                for (int s = 0; s < S; s++) {
                    acc[s].x += t[s].x; acc[s].y += t[s].y;
                    acc[s].z += t[s].z; acc[s].w += t[s].w;
                }
            }
        }
        // stage x into this warp's smem slice (local rows lr+8m)
        #pragma unroll
        for (int m = 0; m < 4; m++)
            #pragma unroll
            for (int v = 0; v < PFR; v++) {
                float* p = &sxw[(lr + 8 * m) * PAD + 4 * q + 16 * v];
                *(float4*)p = acc[m * PFR + v];
            }
        __syncwarp();

        // ---- hidden: hid = relu(x @ W1 + b1) ----
        // Accumulators: 4 rows x 4 col-pairs, packed f32x2
        unsigned long long h2[16];
        {
            float4 bb0 = *(const float4*)&sb1[q * 8];
            float4 bb1 = *(const float4*)&sb1[q * 8 + 4];
            unsigned long long bp[4] = {pack2(bb0.x, bb0.y), pack2(bb0.z, bb0.w),
                                        pack2(bb1.x, bb1.y), pack2(bb1.z, bb1.w)};
            #pragma unroll
            for (int m = 0; m < 4; m++)
                #pragma unroll
                for (int p = 0; p < 4; p++) h2[m * 4 + p] = bp[p];
        }
        #pragma unroll
        for (int kb = 0; kb < DIN / 4; kb++) {
            float4 xq0 = *(const float4*)&sxw[(lr +  0) * PAD + kb * 4];
            float4 xq1 = *(const float4*)&sxw[(lr +  8) * PAD + kb * 4];
            float4 xq2 = *(const float4*)&sxw[(lr + 16) * PAD + kb * 4];
            float4 xq3 = *(const float4*)&sxw[(lr + 24) * PAD + kb * 4];
            float x0[4] = {xq0.x, xq0.y, xq0.z, xq0.w};
            float x1[4] = {xq1.x, xq1.y, xq1.z, xq1.w};
            float x2[4] = {xq2.x, xq2.y, xq2.z, xq2.w};
            float x3[4] = {xq3.x, xq3.y, xq3.z, xq3.w};
            #pragma unroll
            for (int kk = 0; kk < 4; kk++) {
                int k = kb * 4 + kk;
                float4 w0 = *(const float4*)&sW1[k * 32 + q * 8];
                float4 w1 = *(const float4*)&sW1[k * 32 + q * 8 + 4];
                unsigned long long wp[4] = {pack2(w0.x, w0.y), pack2(w0.z, w0.w),
                                            pack2(w1.x, w1.y), pack2(w1.z, w1.w)};
                unsigned long long xa0 = pack2dup(x0[kk]);
                unsigned long long xa1 = pack2dup(x1[kk]);
                unsigned long long xa2 = pack2dup(x2[kk]);
                unsigned long long xa3 = pack2dup(x3[kk]);
                #pragma unroll
                for (int p = 0; p < 4; p++) {
                    fma2(h2[ 0 + p], xa0, wp[p]);
                    fma2(h2[ 4 + p], xa1, wp[p]);
                    fma2(h2[ 8 + p], xa2, wp[p]);
                    fma2(h2[12 + p], xa3, wp[p]);
                }
            }
        }
        __syncwarp();   // all x reads done before hid overwrites the buffer
        #pragma unroll
        for (int m = 0; m < 4; m++) {
            float2 p0 = unpack2(h2[m * 4 + 0]);
            float2 p1 = unpack2(h2[m * 4 + 1]);
            float2 p2 = unpack2(h2[m * 4 + 2]);
            float2 p3 = unpack2(h2[m * 4 + 3]);
            float* p = &sxw[(lr + 8 * m) * PAD + q * 8];
            ((float4*)p)[0] = make_float4(fmaxf(p0.x, 0.f), fmaxf(p0.y, 0.f),
                                          fmaxf(p1.x, 0.f), fmaxf(p1.y, 0.f));
            ((float4*)p)[1] = make_float4(fmaxf(p2.x, 0.f), fmaxf(p2.y, 0.f),
                                          fmaxf(p3.x, 0.f), fmaxf(p3.y, 0.f));
        }
        __syncwarp();

        // ---- output: out = hid @ W2 + b2 ----
        unsigned long long o2[16];
        {
            float4 bb0 = *(const float4*)&sb2[q * 8];
            float4 bb1 = *(const float4*)&sb2[q * 8 + 4];
            unsigned long long bp[4] = {pack2(bb0.x, bb0.y), pack2(bb0.z, bb0.w),
                                        pack2(bb1.x, bb1.y), pack2(bb1.z, bb1.w)};
            #pragma unroll
            for (int m = 0; m < 4; m++)
                #pragma unroll
                for (int p = 0; p < 4; p++) o2[m * 4 + p] = bp[p];
        }
        #pragma unroll
        for (int jb = 0; jb < 8; jb++) {
            float4 hq0 = *(const float4*)&sxw[(lr +  0) * PAD + jb * 4];
            float4 hq1 = *(const float4*)&sxw[(lr +  8) * PAD + jb * 4];
            float4 hq2 = *(const float4*)&sxw[(lr + 16) * PAD + jb * 4];
            float4 hq3 = *(const float4*)&sxw[(lr + 24) * PAD + jb * 4];
            float h0[4] = {hq0.x, hq0.y, hq0.z, hq0.w};
            float h1[4] = {hq1.x, hq1.y, hq1.z, hq1.w};
            float h2v[4] = {hq2.x, hq2.y, hq2.z, hq2.w};
            float h3[4] = {hq3.x, hq3.y, hq3.z, hq3.w};
            #pragma unroll
            for (int jj = 0; jj < 4; jj++) {
                int j = jb * 4 + jj;
                float4 w0 = *(const float4*)&sW2[j * 32 + q * 8];
                float4 w1 = *(const float4*)&sW2[j * 32 + q * 8 + 4];
                unsigned long long wp[4] = {pack2(w0.x, w0.y), pack2(w0.z, w0.w),
                                            pack2(w1.x, w1.y), pack2(w1.z, w1.w)};
                unsigned long long ha0 = pack2dup(h0[jj]);
                unsigned long long ha1 = pack2dup(h1[jj]);
                unsigned long long ha2 = pack2dup(h2v[jj]);
                unsigned long long ha3 = pack2dup(h3[jj]);
                #pragma unroll
                for (int p = 0; p < 4; p++) {
                    fma2(o2[ 0 + p], ha0, wp[p]);
                    fma2(o2[ 4 + p], ha1, wp[p]);
                    fma2(o2[ 8 + p], ha2, wp[p]);
                    fma2(o2[12 + p], ha3, wp[p]);
                }
            }
        }
        __syncwarp();   // hid reads done before next iteration stages x

        // unpack output accumulators
        float oacc[32];
        #pragma unroll
        for (int m = 0; m < 4; m++) {
            float2 p0 = unpack2(o2[m * 4 + 0]);
            float2 p1 = unpack2(o2[m * 4 + 1]);
            float2 p2 = unpack2(o2[m * 4 + 2]);
            float2 p3 = unpack2(o2[m * 4 + 3]);
            oacc[m*8+0] = p0.x; oacc[m*8+1] = p0.y;
            oacc[m*8+2] = p1.x; oacc[m*8+3] = p1.y;
            oacc[m*8+4] = p2.x; oacc[m*8+5] = p2.y;
            oacc[m*8+6] = p3.x; oacc[m*8+7] = p3.y;
        }

        if (!POOL) {
            #pragma unroll
            for (int m = 0; m < 4; m++) {
                int grow = half * 32 + lr + 8 * m;
                float* out = g_h[out_buf] + (size_t)n * (NMAX * 32) + grow * 32 + q * 8;
                float4 o0 = make_float4(oacc[m*8+0], oacc[m*8+1], oacc[m*8+2], oacc[m*8+3]);
                float4 o1 = make_float4(oacc[m*8+4], oacc[m*8+5], oacc[m*8+6], oacc[m*8+7]);
                if (RELU_OUT) {
                    o0.x = fmaxf(o0.x, 0.f); o0.y = fmaxf(o0.y, 0.f);
                    o0.z = fmaxf(o0.z, 0.f); o0.w = fmaxf(o0.w, 0.f);
                    o1.x = fmaxf(o1.x, 0.f); o1.y = fmaxf(o1.y, 0.f);
                    o1.z = fmaxf(o1.z, 0.f); o1.w = fmaxf(o1.w, 0.f);
                }
                ((float4*)out)[0] = o0;
                ((float4*)out)[1] = o1;
            }
        } else {
            // local sum over this lane's 4 rows
            float o[8];
            #pragma unroll
            for (int i = 0; i < 8; i++)
                o[i] = oacc[i] + oacc[8 + i] + oacc[16 + i] + oacc[24 + i];
            // reduce over lr (lane bits 2..4)
            #pragma unroll
            for (int s = 4; s <= 16; s <<= 1) {
                #pragma unroll
                for (int i = 0; i < 8; i++)
                    o[i] += __shfl_xor_sync(0xffffffffu, o[i], s);
            }
            if (lane < 4) {
                float* p = &g_pool[n * 64 + half * 32 + q * 8];
                ((float4*)p)[0] = make_float4(o[0], o[1], o[2], o[3]);
                ((float4*)p)[1] = make_float4(o[4], o[5], o[6], o[7]);
            }
        }
    }
}

// Reduce the 2 per-half partials into the final [NSUM, 32] output.
__global__ void k_pool_reduce(float* __restrict__ dout) {
    int i = blockIdx.x * blockDim.x + threadIdx.x;   // i = n*32 + c
    if (i < NSUM * 32) {
        int n = i >> 5, c = i & 31;
        dout[i] = g_pool[n * 64 + c] + g_pool[n * 64 + 32 + c];
    }
}

// ---------------------------------------------------------------------------
extern "C" void kernel_launch(void* const* d_in, const int* in_sizes, int n_in,
                              void* d_out, int out_size)
{
    const float* W    = (const float*)d_in[0];   // [6400, 64, 16]
    const int*   ei   = (const int*)d_in[1];     // [2, E] row-major
    const float* eps  = (const float*)d_in[2];   // [3]
    const float* W1_0 = (const float*)d_in[3];
    const float* b1_0 = (const float*)d_in[4];
    const float* W2_0 = (const float*)d_in[5];
    const float* b2_0 = (const float*)d_in[6];
    const float* W1_1 = (const float*)d_in[7];
    const float* b1_1 = (const float*)d_in[8];
    const float* W2_1 = (const float*)d_in[9];
    const float* b2_1 = (const float*)d_in[10];
    const float* W1_2 = (const float*)d_in[11];
    const float* b1_2 = (const float*)d_in[12];
    const float* W2_2 = (const float*)d_in[13];
    const float* b2_2 = (const float*)d_in[14];
    float* out = (float*)d_out;

    const int* src = ei;
    const int* dst = ei + EDGES;

    // CSR build (g_cnt is zero at load and re-zeroed by k_scan each call)
    k_count<<<(EDGES + 255) / 256, 256>>>(dst);          // launch 0
    k_scan<<<1, 1024>>>();                                // launch 1
    k_scatter<<<(EDGES + 255) / 256, 256>>>(src, dst);   // launch 2

    const int GRID = 296;   // one persistent wave: 2 blocks x 148 SMs

    // Layer 0: input W (D=16) -> g_h[0]  (relu after MLP)   -- launch 3
    k_layer<16, true, false><<<GRID, 256>>>(W, 0, 0, eps, 0,
                                            W1_0, b1_0, W2_0, b2_0);
    // Layer 1: g_h[0] -> g_h[1]  (relu after MLP)           -- launch 4
    k_layer<32, true, false><<<GRID, 256>>>(nullptr, 0, 1, eps, 1,
                                            W1_1, b1_1, W2_1, b2_1);
    // Layer 2: g_h[1] -> per-half pool partials (no relu)   -- launch 5
    k_layer<32, false, true><<<GRID, 256>>>(nullptr, 1, 0, eps, 2,
                                            W1_2, b1_2, W2_2, b2_2);
    // Final: reduce 2 half partials per node                -- launch 6
    k_pool_reduce<<<(NSUM * 32 + 255) / 256, 256>>>(out);
}

// round 11
// speedup vs baseline: 1.0765x; 1.0227x over previous
#include <cuda_runtime.h>

// Problem constants (fixed shapes per reference)
#define NSUM 6400
#define NMAX 64
#define MDIM 16
#define HDIM 32
#define ODIM 32
#define EDGES 51200

// Scratch: ping/pong node-feature buffers + CSR structures.
__device__ float g_h[2][NSUM * NMAX * HDIM];   // 2 x 52.4 MB
__device__ int g_cnt[NSUM];                    // zero-init at load; k_scan re-zeroes
__device__ int g_off[NSUM + 1];
__device__ int g_cur[NSUM];
__device__ int g_esrc[EDGES];

// ---- packed fp32x2 helpers (Blackwell dual-FMA; full fp32 precision) ----
__device__ __forceinline__ unsigned long long pack2(float lo, float hi) {
    unsigned long long r;
    asm("mov.b64 %0, {%1, %2};" : "=l"(r) : "f"(lo), "f"(hi));
    return r;
}
__device__ __forceinline__ unsigned long long pack2dup(float v) {
    unsigned long long r;
    asm("mov.b64 %0, {%1, %1};" : "=l"(r) : "f"(v));
    return r;
}
__device__ __forceinline__ void fma2(unsigned long long& d,
                                     unsigned long long a, unsigned long long b) {
    asm("fma.rn.f32x2 %0, %1, %2, %0;" : "+l"(d) : "l"(a), "l"(b));
}
__device__ __forceinline__ float2 unpack2(unsigned long long v) {
    float lo, hi;
    asm("mov.b64 {%0, %1}, %2;" : "=f"(lo), "=f"(hi) : "l"(v));
    return make_float2(lo, hi);
}

// ---------------------------------------------------------------------------
// CSR build: count -> scan (self-cleaning) -> scatter
// ---------------------------------------------------------------------------
__global__ void k_count(const int* __restrict__ dst) {
    int e = blockIdx.x * blockDim.x + threadIdx.x;
    if (e < EDGES) atomicAdd(&g_cnt[dst[e]], 1);
}

__global__ void k_scan() {
    __shared__ int part[1024];
    int tid = threadIdx.x;
    const int CH = (NSUM + 1023) / 1024;  // 7
    int base = tid * CH;
    int s = 0;
    #pragma unroll
    for (int i = 0; i < CH; i++) {
        int idx = base + i;
        if (idx < NSUM) s += g_cnt[idx];
    }
    part[tid] = s;
    __syncthreads();
    int own = s;
    for (int d = 1; d < 1024; d <<= 1) {
        int v = (tid >= d) ? part[tid - d] : 0;
        __syncthreads();
        part[tid] += v;
        __syncthreads();
    }
    int run = part[tid] - own;
    #pragma unroll
    for (int i = 0; i < CH; i++) {
        int idx = base + i;
        if (idx < NSUM) {
            g_off[idx] = run;
            g_cur[idx] = run;
            run += g_cnt[idx];
            g_cnt[idx] = 0;          // self-clean for the next replay
        }
    }
    if (tid == 1023) g_off[NSUM] = EDGES;
}

__global__ void k_scatter(const int* __restrict__ src, const int* __restrict__ dst) {
    int e = blockIdx.x * blockDim.x + threadIdx.x;
    if (e < EDGES) {
        int p = atomicAdd(&g_cur[dst[e]], 1);
        g_esrc[p] = src[e];
    }
}

// ---------------------------------------------------------------------------
// Warp-per-NODE fused GIN layer (64 rows per warp).
// Lane (lr = lane>>2, q = lane&3) owns 8 rows {lr+8m, m=0..7} and 8 output
// columns [q*8, q*8+8) held as 4 f32x2 column-pairs per row.
//   - weight LDS amortized over 64 rows (halved vs 32-row units)
//   - edge list walked once per node per layer
//   - gather addressing via base pointer + constant strides (immediate
//     offsets in LDG, no index registers)
//   - POOL layer reduces fully in-warp and writes dout directly
// Dynamic smem: 8 warps x 64 x 36 floats (x/hid union).
// ---------------------------------------------------------------------------
template <int DIN, bool RELU_OUT, bool POOL>
__global__ __launch_bounds__(256, 2) void k_layer(
    const float* __restrict__ ext_in, int in_buf, int out_buf,
    const float* __restrict__ epsv, int layer,
    const float* __restrict__ W1, const float* __restrict__ b1,
    const float* __restrict__ W2, const float* __restrict__ b2,
    float* __restrict__ dout)
{
    constexpr int R4   = DIN / 4;          // float4 per row
    constexpr int PFR  = R4 / 4;           // float4 per lane per row (1 or 2)
    constexpr int V4   = NMAX * R4;        // float4 per node block
    constexpr int PAD  = 36;               // row stride (floats); 144B = 16B-aligned

    __shared__ float sW1[DIN * 32];
    __shared__ float sW2[32 * 32];
    __shared__ float sb1[32], sb2[32];
    extern __shared__ float sxh_dyn[];     // 8 x 64 x PAD floats

    int tid = threadIdx.x;
    int wid = tid >> 5, lane = tid & 31;
    int lr = lane >> 2, q = lane & 3;

    for (int i = tid; i < DIN * 32; i += 256) sW1[i] = W1[i];
    for (int i = tid; i < 32 * 32;  i += 256) sW2[i] = W2[i];
    if (tid < 32) { sb1[tid] = b1[tid]; sb2[tid] = b2[tid]; }
    float ep1 = 1.0f + epsv[layer];
    __syncthreads();

    const float*  h_in = ext_in ? ext_in : g_h[in_buf];
    const float4* h4   = (const float4*)h_in;
    float* sxw = sxh_dyn + wid * (64 * PAD);
    const int lanesl = lr * R4 + q;        // lane's base float4 slot within node

    for (int n = blockIdx.x * 8 + wid; n < NSUM; n += gridDim.x * 8) {
        // ---- gather: acc = (1+eps)*h[n] + sum_neighbors h[src] ----
        // acc[m][v] corresponds to node-slot lanesl + m*(8*R4) + 4*v
        float4 acc[8 * PFR];
        {
            const float4* hn = h4 + (size_t)n * V4 + lanesl;
            #pragma unroll
            for (int m = 0; m < 8; m++)
                #pragma unroll
                for (int v = 0; v < PFR; v++) {
                    float4 t = hn[m * (8 * R4) + 4 * v];
                    acc[m * PFR + v] = make_float4(ep1 * t.x, ep1 * t.y,
                                                   ep1 * t.z, ep1 * t.w);
                }
        }
        int e0 = g_off[n], e1 = g_off[n + 1];
        for (int base = e0; base < e1; base += 32) {
            int cnt = min(32, e1 - base);
            int id = (lane < cnt) ? g_esrc[base + lane] : 0;
            for (int e = 0; e < cnt; e++) {
                int sa = __shfl_sync(0xffffffffu, id, e);
                const float4* pa = h4 + (size_t)sa * V4 + lanesl;
                #pragma unroll
                for (int m = 0; m < 8; m++)
                    #pragma unroll
                    for (int v = 0; v < PFR; v++) {
                        float4 t = pa[m * (8 * R4) + 4 * v];
                        float4& a = acc[m * PFR + v];
                        a.x += t.x; a.y += t.y; a.z += t.z; a.w += t.w;
                    }
            }
        }
        // stage x into this warp's smem slice (rows lr+8m)
        #pragma unroll
        for (int m = 0; m < 8; m++)
            #pragma unroll
            for (int v = 0; v < PFR; v++) {
                float* p = &sxw[(lr + 8 * m) * PAD + 4 * q + 16 * v];
                *(float4*)p = acc[m * PFR + v];
            }
        __syncwarp();

        // ---- hidden: hid = relu(x @ W1 + b1); lane: 8 rows x 4 col-pairs ----
        unsigned long long h2[32];
        {
            float4 bb0 = *(const float4*)&sb1[q * 8];
            float4 bb1 = *(const float4*)&sb1[q * 8 + 4];
            unsigned long long bp[4] = {pack2(bb0.x, bb0.y), pack2(bb0.z, bb0.w),
                                        pack2(bb1.x, bb1.y), pack2(bb1.z, bb1.w)};
            #pragma unroll
            for (int m = 0; m < 8; m++)
                #pragma unroll
                for (int p = 0; p < 4; p++) h2[m * 4 + p] = bp[p];
        }
        #pragma unroll
        for (int kb = 0; kb < DIN / 4; kb++) {
            float4 xq[8];
            #pragma unroll
            for (int m = 0; m < 8; m++)
                xq[m] = *(const float4*)&sxw[(lr + 8 * m) * PAD + kb * 4];
            #pragma unroll
            for (int kk = 0; kk < 4; kk++) {
                int k = kb * 4 + kk;
                float4 w0 = *(const float4*)&sW1[k * 32 + q * 8];
                float4 w1 = *(const float4*)&sW1[k * 32 + q * 8 + 4];
                unsigned long long wp[4] = {pack2(w0.x, w0.y), pack2(w0.z, w0.w),
                                            pack2(w1.x, w1.y), pack2(w1.z, w1.w)};
                #pragma unroll
                for (int m = 0; m < 8; m++) {
                    float xv = (kk == 0) ? xq[m].x : (kk == 1) ? xq[m].y
                             : (kk == 2) ? xq[m].z : xq[m].w;
                    unsigned long long xa = pack2dup(xv);
                    #pragma unroll
                    for (int p = 0; p < 4; p++)
                        fma2(h2[m * 4 + p], xa, wp[p]);
                }
            }
        }
        __syncwarp();   // all x reads done before hid overwrites the buffer
        #pragma unroll
        for (int m = 0; m < 8; m++) {
            float2 p0 = unpack2(h2[m * 4 + 0]);
            float2 p1 = unpack2(h2[m * 4 + 1]);
            float2 p2 = unpack2(h2[m * 4 + 2]);
            float2 p3 = unpack2(h2[m * 4 + 3]);
            float* p = &sxw[(lr + 8 * m) * PAD + q * 8];
            ((float4*)p)[0] = make_float4(fmaxf(p0.x, 0.f), fmaxf(p0.y, 0.f),
                                          fmaxf(p1.x, 0.f), fmaxf(p1.y, 0.f));
            ((float4*)p)[1] = make_float4(fmaxf(p2.x, 0.f), fmaxf(p2.y, 0.f),
                                          fmaxf(p3.x, 0.f), fmaxf(p3.y, 0.f));
        }
        __syncwarp();

        // ---- output: out = hid @ W2 + b2 ----
        unsigned long long o2[32];
        {
            float4 bb0 = *(const float4*)&sb2[q * 8];
            float4 bb1 = *(const float4*)&sb2[q * 8 + 4];
            unsigned long long bp[4] = {pack2(bb0.x, bb0.y), pack2(bb0.z, bb0.w),
                                        pack2(bb1.x, bb1.y), pack2(bb1.z, bb1.w)};
            #pragma unroll
            for (int m = 0; m < 8; m++)
                #pragma unroll
                for (int p = 0; p < 4; p++) o2[m * 4 + p] = bp[p];
        }
        #pragma unroll
        for (int jb = 0; jb < 8; jb++) {
            float4 hq[8];
            #pragma unroll
            for (int m = 0; m < 8; m++)
                hq[m] = *(const float4*)&sxw[(lr + 8 * m) * PAD + jb * 4];
            #pragma unroll
            for (int jj = 0; jj < 4; jj++) {
                int j = jb * 4 + jj;
                float4 w0 = *(const float4*)&sW2[j * 32 + q * 8];
                float4 w1 = *(const float4*)&sW2[j * 32 + q * 8 + 4];
                unsigned long long wp[4] = {pack2(w0.x, w0.y), pack2(w0.z, w0.w),
                                            pack2(w1.x, w1.y), pack2(w1.z, w1.w)};
                #pragma unroll
                for (int m = 0; m < 8; m++) {
                    float hv = (jj == 0) ? hq[m].x : (jj == 1) ? hq[m].y
                             : (jj == 2) ? hq[m].z : hq[m].w;
                    unsigned long long ha = pack2dup(hv);
                    #pragma unroll
                    for (int p = 0; p < 4; p++)
                        fma2(o2[m * 4 + p], ha, wp[p]);
                }
            }
        }
        __syncwarp();   // hid reads done before next iteration stages x

        if (!POOL) {
            #pragma unroll
            for (int m = 0; m < 8; m++) {
                float2 p0 = unpack2(o2[m * 4 + 0]);
                float2 p1 = unpack2(o2[m * 4 + 1]);
                float2 p2 = unpack2(o2[m * 4 + 2]);
                float2 p3 = unpack2(o2[m * 4 + 3]);
                float4 v0 = make_float4(p0.x, p0.y, p1.x, p1.y);
                float4 v1 = make_float4(p2.x, p2.y, p3.x, p3.y);
                if (RELU_OUT) {
                    v0.x = fmaxf(v0.x, 0.f); v0.y = fmaxf(v0.y, 0.f);
                    v0.z = fmaxf(v0.z, 0.f); v0.w = fmaxf(v0.w, 0.f);
                    v1.x = fmaxf(v1.x, 0.f); v1.y = fmaxf(v1.y, 0.f);
                    v1.z = fmaxf(v1.z, 0.f); v1.w = fmaxf(v1.w, 0.f);
                }
                int grow = lr + 8 * m;
                float* out = g_h[out_buf] + (size_t)n * (NMAX * 32) + grow * 32 + q * 8;
                ((float4*)out)[0] = v0;
                ((float4*)out)[1] = v1;
            }
        } else {
            // sum over lane's 8 rows, then over lr (lane bits 2..4) -> all 64
            float o[8];
            #pragma unroll
            for (int i = 0; i < 8; i++) o[i] = 0.0f;
            #pragma unroll
            for (int m = 0; m < 8; m++) {
                float2 p0 = unpack2(o2[m * 4 + 0]);
                float2 p1 = unpack2(o2[m * 4 + 1]);
                float2 p2 = unpack2(o2[m * 4 + 2]);
                float2 p3 = unpack2(o2[m * 4 + 3]);
                o[0] += p0.x; o[1] += p0.y; o[2] += p1.x; o[3] += p1.y;
                o[4] += p2.x; o[5] += p2.y; o[6] += p3.x; o[7] += p3.y;
            }
            #pragma unroll
            for (int s = 4; s <= 16; s <<= 1) {
                #pragma unroll
                for (int i = 0; i < 8; i++)
                    o[i] += __shfl_xor_sync(0xffffffffu, o[i], s);
            }
            if (lane < 4) {
                float* p = &dout[n * 32 + q * 8];
                ((float4*)p)[0] = make_float4(o[0], o[1], o[2], o[3]);
                ((float4*)p)[1] = make_float4(o[4], o[5], o[6], o[7]);
            }
        }
    }
}

// ---------------------------------------------------------------------------
extern "C" void kernel_launch(void* const* d_in, const int* in_sizes, int n_in,
                              void* d_out, int out_size)
{
    const float* W    = (const float*)d_in[0];   // [6400, 64, 16]
    const int*   ei   = (const int*)d_in[1];     // [2, E] row-major
    const float* eps  = (const float*)d_in[2];   // [3]
    const float* W1_0 = (const float*)d_in[3];
    const float* b1_0 = (const float*)d_in[4];
    const float* W2_0 = (const float*)d_in[5];
    const float* b2_0 = (const float*)d_in[6];
    const float* W1_1 = (const float*)d_in[7];
    const float* b1_1 = (const float*)d_in[8];
    const float* W2_1 = (const float*)d_in[9];
    const float* b2_1 = (const float*)d_in[10];
    const float* W1_2 = (const float*)d_in[11];
    const float* b1_2 = (const float*)d_in[12];
    const float* W2_2 = (const float*)d_in[13];
    const float* b2_2 = (const float*)d_in[14];
    float* out = (float*)d_out;

    const int* src = ei;
    const int* dst = ei + EDGES;

    const int DYN = 8 * 64 * 36 * (int)sizeof(float);   // 73728 B
    cudaFuncSetAttribute(k_layer<16, true, false>,
                         cudaFuncAttributeMaxDynamicSharedMemorySize, DYN);
    cudaFuncSetAttribute(k_layer<32, true, false>,
                         cudaFuncAttributeMaxDynamicSharedMemorySize, DYN);
    cudaFuncSetAttribute(k_layer<32, false, true>,
                         cudaFuncAttributeMaxDynamicSharedMemorySize, DYN);

    // CSR build (g_cnt is zero at load and re-zeroed by k_scan each call)
    k_count<<<(EDGES + 255) / 256, 256>>>(dst);          // launch 0
    k_scan<<<1, 1024>>>();                                // launch 1
    k_scatter<<<(EDGES + 255) / 256, 256>>>(src, dst);   // launch 2

    const int GRID = 296;   // one persistent wave: 2 blocks x 148 SMs

    // Layer 0: input W (D=16) -> g_h[0]  (relu after MLP)   -- launch 3
    k_layer<16, true, false><<<GRID, 256, DYN>>>(W, 0, 0, eps, 0,
                                                 W1_0, b1_0, W2_0, b2_0, nullptr);
    // Layer 1: g_h[0] -> g_h[1]  (relu after MLP)           -- launch 4
    k_layer<32, true, false><<<GRID, 256, DYN>>>(nullptr, 0, 1, eps, 1,
                                                 W1_1, b1_1, W2_1, b2_1, nullptr);
    // Layer 2: g_h[1] -> pooled d_out directly (no relu)    -- launch 5
    k_layer<32, false, true><<<GRID, 256, DYN>>>(nullptr, 1, 0, eps, 2,
                                                 W1_2, b1_2, W2_2, b2_2, out);
}

// round 12
// speedup vs baseline: 1.0811x; 1.0042x over previous
#include <cuda_runtime.h>

// Problem constants (fixed shapes per reference)
#define NSUM 6400
#define NMAX 64
#define MDIM 16
#define HDIM 32
#define ODIM 32
#define EDGES 51200

// Scratch: ping/pong node-feature buffers + CSR structures.
__device__ float g_h[2][NSUM * NMAX * HDIM];   // 2 x 52.4 MB
__device__ int g_cnt[NSUM];                    // zero-init at load; k_scan re-zeroes
__device__ int g_off[NSUM + 1];
__device__ int g_cur[NSUM];
__device__ int g_esrc[EDGES];

// ---- packed fp32x2 helpers (Blackwell dual-FMA; full fp32 precision) ----
__device__ __forceinline__ unsigned long long pack2(float lo, float hi) {
    unsigned long long r;
    asm("mov.b64 %0, {%1, %2};" : "=l"(r) : "f"(lo), "f"(hi));
    return r;
}
__device__ __forceinline__ unsigned long long pack2dup(float v) {
    unsigned long long r;
    asm("mov.b64 %0, {%1, %1};" : "=l"(r) : "f"(v));
    return r;
}
__device__ __forceinline__ void fma2(unsigned long long& d,
                                     unsigned long long a, unsigned long long b) {
    asm("fma.rn.f32x2 %0, %1, %2, %0;" : "+l"(d) : "l"(a), "l"(b));
}
__device__ __forceinline__ float2 unpack2(unsigned long long v) {
    float lo, hi;
    asm("mov.b64 {%0, %1}, %2;" : "=f"(lo), "=f"(hi) : "l"(v));
    return make_float2(lo, hi);
}

// ---------------------------------------------------------------------------
// CSR build: count -> scan (self-cleaning) -> scatter
// ---------------------------------------------------------------------------
__global__ void k_count(const int* __restrict__ dst) {
    int e = blockIdx.x * blockDim.x + threadIdx.x;
    if (e < EDGES) atomicAdd(&g_cnt[dst[e]], 1);
}

__global__ void k_scan() {
    __shared__ int part[1024];
    int tid = threadIdx.x;
    const int CH = (NSUM + 1023) / 1024;  // 7
    int base = tid * CH;
    int s = 0;
    #pragma unroll
    for (int i = 0; i < CH; i++) {
        int idx = base + i;
        if (idx < NSUM) s += g_cnt[idx];
    }
    part[tid] = s;
    __syncthreads();
    int own = s;
    for (int d = 1; d < 1024; d <<= 1) {
        int v = (tid >= d) ? part[tid - d] : 0;
        __syncthreads();
        part[tid] += v;
        __syncthreads();
    }
    int run = part[tid] - own;
    #pragma unroll
    for (int i = 0; i < CH; i++) {
        int idx = base + i;
        if (idx < NSUM) {
            g_off[idx] = run;
            g_cur[idx] = run;
            run += g_cnt[idx];
            g_cnt[idx] = 0;          // self-clean for the next replay
        }
    }
    if (tid == 1023) g_off[NSUM] = EDGES;
}

__global__ void k_scatter(const int* __restrict__ src, const int* __restrict__ dst) {
    int e = blockIdx.x * blockDim.x + threadIdx.x;
    if (e < EDGES) {
        int p = atomicAdd(&g_cur[dst[e]], 1);
        g_esrc[p] = src[e];
    }
}

// ---------------------------------------------------------------------------
// Warp-per-NODE fused GIN layer (64 rows per warp).
// Lane (lr = lane>>2, q = lane&3) owns 8 rows {lr+8m, m=0..7} and 8 output
// columns [q*8, q*8+8) held as 4 f32x2 column-pairs per row.
//   gather : D=16 -> 2-edge-wide register-buffered loads (halves exposed
//            L2 latency); D=32 -> pointer-pipelined (next edge's shfl+
//            address hoisted off the critical path).
//   MLP    : f32x2 dual-FMA; weight LDS amortized over the full 64 rows.
//   POOL   : in-warp reduction, writes dout directly.
// Dynamic smem: 8 warps x 64 x 36 floats (x/hid union).
// ---------------------------------------------------------------------------
template <int DIN, bool RELU_OUT, bool POOL>
__global__ __launch_bounds__(256, 2) void k_layer(
    const float* __restrict__ ext_in, int in_buf, int out_buf,
    const float* __restrict__ epsv, int layer,
    const float* __restrict__ W1, const float* __restrict__ b1,
    const float* __restrict__ W2, const float* __restrict__ b2,
    float* __restrict__ dout)
{
    constexpr int R4   = DIN / 4;          // float4 per row
    constexpr int PFR  = R4 / 4;           // float4 per lane per row (1 or 2)
    constexpr int V4   = NMAX * R4;        // float4 per node block
    constexpr int PAD  = 36;               // row stride (floats); 144B = 16B-aligned

    __shared__ float sW1[DIN * 32];
    __shared__ float sW2[32 * 32];
    __shared__ float sb1[32], sb2[32];
    extern __shared__ float sxh_dyn[];     // 8 x 64 x PAD floats

    int tid = threadIdx.x;
    int wid = tid >> 5, lane = tid & 31;
    int lr = lane >> 2, q = lane & 3;

    for (int i = tid; i < DIN * 32; i += 256) sW1[i] = W1[i];
    for (int i = tid; i < 32 * 32;  i += 256) sW2[i] = W2[i];
    if (tid < 32) { sb1[tid] = b1[tid]; sb2[tid] = b2[tid]; }
    float ep1 = 1.0f + epsv[layer];
    __syncthreads();

    const float*  h_in = ext_in ? ext_in : g_h[in_buf];
    const float4* h4   = (const float4*)h_in;
    float* sxw = sxh_dyn + wid * (64 * PAD);
    const int lanesl = lr * R4 + q;        // lane's base float4 slot within node

    for (int n = blockIdx.x * 8 + wid; n < NSUM; n += gridDim.x * 8) {
        // ---- gather: acc = (1+eps)*h[n] + sum_neighbors h[src] ----
        float4 acc[8 * PFR];
        {
            const float4* hn = h4 + (size_t)n * V4 + lanesl;
            #pragma unroll
            for (int m = 0; m < 8; m++)
                #pragma unroll
                for (int v = 0; v < PFR; v++) {
                    float4 t = hn[m * (8 * R4) + 4 * v];
                    acc[m * PFR + v] = make_float4(ep1 * t.x, ep1 * t.y,
                                                   ep1 * t.z, ep1 * t.w);
                }
        }
        int e0 = g_off[n], e1 = g_off[n + 1];
        for (int base = e0; base < e1; base += 32) {
            int cnt = min(32, e1 - base);
            int id = (lane < cnt) ? g_esrc[base + lane] : 0;
            int e = 0;
            if (PFR == 1) {
                // D=16: 2-edge-wide register-buffered gather
                for (; e + 2 <= cnt; e += 2) {
                    int sa = __shfl_sync(0xffffffffu, id, e);
                    int sb = __shfl_sync(0xffffffffu, id, e + 1);
                    const float4* pa = h4 + (size_t)sa * V4 + lanesl;
                    const float4* pb = h4 + (size_t)sb * V4 + lanesl;
                    float4 ta[8], tb[8];
                    #pragma unroll
                    for (int m = 0; m < 8; m++) ta[m] = pa[m * (8 * R4)];
                    #pragma unroll
                    for (int m = 0; m < 8; m++) tb[m] = pb[m * (8 * R4)];
                    #pragma unroll
                    for (int m = 0; m < 8; m++) {
                        acc[m].x += ta[m].x; acc[m].y += ta[m].y;
                        acc[m].z += ta[m].z; acc[m].w += ta[m].w;
                    }
                    #pragma unroll
                    for (int m = 0; m < 8; m++) {
                        acc[m].x += tb[m].x; acc[m].y += tb[m].y;
                        acc[m].z += tb[m].z; acc[m].w += tb[m].w;
                    }
                }
                if (e < cnt) {
                    int sa = __shfl_sync(0xffffffffu, id, e);
                    const float4* pa = h4 + (size_t)sa * V4 + lanesl;
                    #pragma unroll
                    for (int m = 0; m < 8; m++) {
                        float4 t = pa[m * (8 * R4)];
                        acc[m].x += t.x; acc[m].y += t.y;
                        acc[m].z += t.z; acc[m].w += t.w;
                    }
                }
            } else {
                // D=32: pointer-pipelined gather (next address precomputed)
                int sa0 = __shfl_sync(0xffffffffu, id, 0);
                const float4* pa = h4 + (size_t)sa0 * V4 + lanesl;
                for (; e < cnt; e++) {
                    int enext = (e + 1 < cnt) ? e + 1 : e;
                    int sn = __shfl_sync(0xffffffffu, id, enext);
                    const float4* pnext = h4 + (size_t)sn * V4 + lanesl;
                    #pragma unroll
                    for (int m = 0; m < 8; m++)
                        #pragma unroll
                        for (int v = 0; v < PFR; v++) {
                            float4 t = pa[m * (8 * R4) + 4 * v];
                            float4& a = acc[m * PFR + v];
                            a.x += t.x; a.y += t.y; a.z += t.z; a.w += t.w;
                        }
                    pa = pnext;
                }
            }
        }
        // stage x into this warp's smem slice (rows lr+8m)
        #pragma unroll
        for (int m = 0; m < 8; m++)
            #pragma unroll
            for (int v = 0; v < PFR; v++) {
                float* p = &sxw[(lr + 8 * m) * PAD + 4 * q + 16 * v];
                *(float4*)p = acc[m * PFR + v];
            }
        __syncwarp();

        // ---- hidden: hid = relu(x @ W1 + b1); lane: 8 rows x 4 col-pairs ----
        unsigned long long h2[32];
        {
            float4 bb0 = *(const float4*)&sb1[q * 8];
            float4 bb1 = *(const float4*)&sb1[q * 8 + 4];
            unsigned long long bp[4] = {pack2(bb0.x, bb0.y), pack2(bb0.z, bb0.w),
                                        pack2(bb1.x, bb1.y), pack2(bb1.z, bb1.w)};
            #pragma unroll
            for (int m = 0; m < 8; m++)
                #pragma unroll
                for (int p = 0; p < 4; p++) h2[m * 4 + p] = bp[p];
        }
        #pragma unroll
        for (int kb = 0; kb < DIN / 4; kb++) {
            float4 xq[8];
            #pragma unroll
            for (int m = 0; m < 8; m++)
                xq[m] = *(const float4*)&sxw[(lr + 8 * m) * PAD + kb * 4];
            #pragma unroll
            for (int kk = 0; kk < 4; kk++) {
                int k = kb * 4 + kk;
                float4 w0 = *(const float4*)&sW1[k * 32 + q * 8];
                float4 w1 = *(const float4*)&sW1[k * 32 + q * 8 + 4];
                unsigned long long wp[4] = {pack2(w0.x, w0.y), pack2(w0.z, w0.w),
                                            pack2(w1.x, w1.y), pack2(w1.z, w1.w)};
                #pragma unroll
                for (int m = 0; m < 8; m++) {
                    float xv = (kk == 0) ? xq[m].x : (kk == 1) ? xq[m].y
                             : (kk == 2) ? xq[m].z : xq[m].w;
                    unsigned long long xa = pack2dup(xv);
                    #pragma unroll
                    for (int p = 0; p < 4; p++)
                        fma2(h2[m * 4 + p], xa, wp[p]);
                }
            }
        }
        __syncwarp();   // all x reads done before hid overwrites the buffer
        #pragma unroll
        for (int m = 0; m < 8; m++) {
            float2 p0 = unpack2(h2[m * 4 + 0]);
            float2 p1 = unpack2(h2[m * 4 + 1]);
            float2 p2 = unpack2(h2[m * 4 + 2]);
            float2 p3 = unpack2(h2[m * 4 + 3]);
            float* p = &sxw[(lr + 8 * m) * PAD + q * 8];
            ((float4*)p)[0] = make_float4(fmaxf(p0.x, 0.f), fmaxf(p0.y, 0.f),
                                          fmaxf(p1.x, 0.f), fmaxf(p1.y, 0.f));
            ((float4*)p)[1] = make_float4(fmaxf(p2.x, 0.f), fmaxf(p2.y, 0.f),
                                          fmaxf(p3.x, 0.f), fmaxf(p3.y, 0.f));
        }
        __syncwarp();

        // ---- output: out = hid @ W2 + b2 ----
        unsigned long long o2[32];
        {
            float4 bb0 = *(const float4*)&sb2[q * 8];
            float4 bb1 = *(const float4*)&sb2[q * 8 + 4];
            unsigned long long bp[4] = {pack2(bb0.x, bb0.y), pack2(bb0.z, bb0.w),
                                        pack2(bb1.x, bb1.y), pack2(bb1.z, bb1.w)};
            #pragma unroll
            for (int m = 0; m < 8; m++)
                #pragma unroll
                for (int p = 0; p < 4; p++) o2[m * 4 + p] = bp[p];
        }
        #pragma unroll
        for (int jb = 0; jb < 8; jb++) {
            float4 hq[8];
            #pragma unroll
            for (int m = 0; m < 8; m++)
                hq[m] = *(const float4*)&sxw[(lr + 8 * m) * PAD + jb * 4];
            #pragma unroll
            for (int jj = 0; jj < 4; jj++) {
                int j = jb * 4 + jj;
                float4 w0 = *(const float4*)&sW2[j * 32 + q * 8];
                float4 w1 = *(const float4*)&sW2[j * 32 + q * 8 + 4];
                unsigned long long wp[4] = {pack2(w0.x, w0.y), pack2(w0.z, w0.w),
                                            pack2(w1.x, w1.y), pack2(w1.z, w1.w)};
                #pragma unroll
                for (int m = 0; m < 8; m++) {
                    float hv = (jj == 0) ? hq[m].x : (jj == 1) ? hq[m].y
                             : (jj == 2) ? hq[m].z : hq[m].w;
                    unsigned long long ha = pack2dup(hv);
                    #pragma unroll
                    for (int p = 0; p < 4; p++)
                        fma2(o2[m * 4 + p], ha, wp[p]);
                }
            }
        }
        __syncwarp();   // hid reads done before next iteration stages x

        if (!POOL) {
            #pragma unroll
            for (int m = 0; m < 8; m++) {
                float2 p0 = unpack2(o2[m * 4 + 0]);
                float2 p1 = unpack2(o2[m * 4 + 1]);
                float2 p2 = unpack2(o2[m * 4 + 2]);
                float2 p3 = unpack2(o2[m * 4 + 3]);
                float4 v0 = make_float4(p0.x, p0.y, p1.x, p1.y);
                float4 v1 = make_float4(p2.x, p2.y, p3.x, p3.y);
                if (RELU_OUT) {
                    v0.x = fmaxf(v0.x, 0.f); v0.y = fmaxf(v0.y, 0.f);
                    v0.z = fmaxf(v0.z, 0.f); v0.w = fmaxf(v0.w, 0.f);
                    v1.x = fmaxf(v1.x, 0.f); v1.y = fmaxf(v1.y, 0.f);
                    v1.z = fmaxf(v1.z, 0.f); v1.w = fmaxf(v1.w, 0.f);
                }
                int grow = lr + 8 * m;
                float* out = g_h[out_buf] + (size_t)n * (NMAX * 32) + grow * 32 + q * 8;
                ((float4*)out)[0] = v0;
                ((float4*)out)[1] = v1;
            }
        } else {
            // sum over lane's 8 rows, then over lr (lane bits 2..4) -> all 64
            float o[8];
            #pragma unroll
            for (int i = 0; i < 8; i++) o[i] = 0.0f;
            #pragma unroll
            for (int m = 0; m < 8; m++) {
                float2 p0 = unpack2(o2[m * 4 + 0]);
                float2 p1 = unpack2(o2[m * 4 + 1]);
                float2 p2 = unpack2(o2[m * 4 + 2]);
                float2 p3 = unpack2(o2[m * 4 + 3]);
                o[0] += p0.x; o[1] += p0.y; o[2] += p1.x; o[3] += p1.y;
                o[4] += p2.x; o[5] += p2.y; o[6] += p3.x; o[7] += p3.y;
            }
            #pragma unroll
            for (int s = 4; s <= 16; s <<= 1) {
                #pragma unroll
                for (int i = 0; i < 8; i++)
                    o[i] += __shfl_xor_sync(0xffffffffu, o[i], s);
            }
            if (lane < 4) {
                float* p = &dout[n * 32 + q * 8];
                ((float4*)p)[0] = make_float4(o[0], o[1], o[2], o[3]);
                ((float4*)p)[1] = make_float4(o[4], o[5], o[6], o[7]);
            }
        }
    }
}

// ---------------------------------------------------------------------------
extern "C" void kernel_launch(void* const* d_in, const int* in_sizes, int n_in,
                              void* d_out, int out_size)
{
    const float* W    = (const float*)d_in[0];   // [6400, 64, 16]
    const int*   ei   = (const int*)d_in[1];     // [2, E] row-major
    const float* eps  = (const float*)d_in[2];   // [3]
    const float* W1_0 = (const float*)d_in[3];
    const float* b1_0 = (const float*)d_in[4];
    const float* W2_0 = (const float*)d_in[5];
    const float* b2_0 = (const float*)d_in[6];
    const float* W1_1 = (const float*)d_in[7];
    const float* b1_1 = (const float*)d_in[8];
    const float* W2_1 = (const float*)d_in[9];
    const float* b2_1 = (const float*)d_in[10];
    const float* W1_2 = (const float*)d_in[11];
    const float* b1_2 = (const float*)d_in[12];
    const float* W2_2 = (const float*)d_in[13];
    const float* b2_2 = (const float*)d_in[14];
    float* out = (float*)d_out;

    const int* src = ei;
    const int* dst = ei + EDGES;

    const int DYN = 8 * 64 * 36 * (int)sizeof(float);   // 73728 B
    cudaFuncSetAttribute(k_layer<16, true, false>,
                         cudaFuncAttributeMaxDynamicSharedMemorySize, DYN);
    cudaFuncSetAttribute(k_layer<32, true, false>,
                         cudaFuncAttributeMaxDynamicSharedMemorySize, DYN);
    cudaFuncSetAttribute(k_layer<32, false, true>,
                         cudaFuncAttributeMaxDynamicSharedMemorySize, DYN);

    // CSR build (g_cnt is zero at load and re-zeroed by k_scan each call)
    k_count<<<(EDGES + 255) / 256, 256>>>(dst);          // launch 0
    k_scan<<<1, 1024>>>();                                // launch 1
    k_scatter<<<(EDGES + 255) / 256, 256>>>(src, dst);   // launch 2

    const int GRID = 296;   // one persistent wave: 2 blocks x 148 SMs

    // Layer 0: input W (D=16) -> g_h[0]  (relu after MLP)   -- launch 3
    k_layer<16, true, false><<<GRID, 256, DYN>>>(W, 0, 0, eps, 0,
                                                 W1_0, b1_0, W2_0, b2_0, nullptr);
    // Layer 1: g_h[0] -> g_h[1]  (relu after MLP)           -- launch 4
    k_layer<32, true, false><<<GRID, 256, DYN>>>(nullptr, 0, 1, eps, 1,
                                                 W1_1, b1_1, W2_1, b2_1, nullptr);
    // Layer 2: g_h[1] -> pooled d_out directly (no relu)    -- launch 5
    k_layer<32, false, true><<<GRID, 256, DYN>>>(nullptr, 1, 0, eps, 2,
                                                 W1_2, b1_2, W2_2, b2_2, out);
}

// round 14
// speedup vs baseline: 1.1668x; 1.0793x over previous
#include <cuda_runtime.h>

// Problem constants (fixed shapes per reference)
#define NSUM 6400
#define NMAX 64
#define MDIM 16
#define HDIM 32
#define ODIM 32
#define EDGES 51200

// Scratch: ping/pong node-feature buffers + CSR structures.
__device__ float g_h[2][NSUM * NMAX * HDIM];   // 2 x 52.4 MB
__device__ int g_cnt[NSUM];                    // zero-init at load; k_scan re-zeroes
__device__ int g_off[NSUM + 1];
__device__ int g_cur[NSUM];
__device__ int g_esrc[EDGES];

// ---- packed fp32x2 helpers (Blackwell dual-FMA; full fp32 precision) ----
__device__ __forceinline__ unsigned long long pack2(float lo, float hi) {
    unsigned long long r;
    asm("mov.b64 %0, {%1, %2};" : "=l"(r) : "f"(lo), "f"(hi));
    return r;
}
__device__ __forceinline__ unsigned long long pack2dup(float v) {
    unsigned long long r;
    asm("mov.b64 %0, {%1, %1};" : "=l"(r) : "f"(v));
    return r;
}
__device__ __forceinline__ void fma2(unsigned long long& d,
                                     unsigned long long a, unsigned long long b) {
    asm("fma.rn.f32x2 %0, %1, %2, %0;" : "+l"(d) : "l"(a), "l"(b));
}
__device__ __forceinline__ float2 unpack2(unsigned long long v) {
    float lo, hi;
    asm("mov.b64 {%0, %1}, %2;" : "=f"(lo), "=f"(hi) : "l"(v));
    return make_float2(lo, hi);
}

// ---------------------------------------------------------------------------
// CSR build: count -> scan (self-cleaning) -> scatter
// ---------------------------------------------------------------------------
__global__ void k_count(const int* __restrict__ dst) {
    int e = blockIdx.x * blockDim.x + threadIdx.x;
    if (e < EDGES) atomicAdd(&g_cnt[dst[e]], 1);
}

__global__ void k_scan() {
    __shared__ int part[1024];
    int tid = threadIdx.x;
    const int CH = (NSUM + 1023) / 1024;  // 7
    int base = tid * CH;
    int s = 0;
    #pragma unroll
    for (int i = 0; i < CH; i++) {
        int idx = base + i;
        if (idx < NSUM) s += g_cnt[idx];
    }
    part[tid] = s;
    __syncthreads();
    int own = s;
    for (int d = 1; d < 1024; d <<= 1) {
        int v = (tid >= d) ? part[tid - d] : 0;
        __syncthreads();
        part[tid] += v;
        __syncthreads();
    }
    int run = part[tid] - own;
    #pragma unroll
    for (int i = 0; i < CH; i++) {
        int idx = base + i;
        if (idx < NSUM) {
            g_off[idx] = run;
            g_cur[idx] = run;
            run += g_cnt[idx];
            g_cnt[idx] = 0;          // self-clean for the next replay
        }
    }
    if (tid == 1023) g_off[NSUM] = EDGES;
}

__global__ void k_scatter(const int* __restrict__ src, const int* __restrict__ dst) {
    int e = blockIdx.x * blockDim.x + threadIdx.x;
    if (e < EDGES) {
        int p = atomicAdd(&g_cur[dst[e]], 1);
        g_esrc[p] = src[e];
    }
}

// ---------------------------------------------------------------------------
// Warp-per-NODE fused GIN layer (64 rows per warp), LINEAR gather mapping.
// Gather: lane owns float4 slots {m*32 + lane, m=0..MV-1} -> every warp-LDG
// is a CONTIGUOUS 512B block (4 L1tex wavefronts, the floor).
// Staging: slot (row, col) = (slot >> SH, (slot & (R4-1))*4); per-m row
// increment is (32 >> SH): 8 for D=16, 4 for D=32.  [R13 bug: was 8 always]
// MLP: lane (lr = lane>>2, q = lane&3) processes rows {lr+8m} x cols
// [q*8, q*8+8) as f32x2 column-pairs.
// POOL: in-warp reduction, writes dout directly.
// Dynamic smem: 8 warps x 64 x 36 floats (x/hid union).
// ---------------------------------------------------------------------------
template <int DIN, bool RELU_OUT, bool POOL>
__global__ __launch_bounds__(256, 2) void k_layer(
    const float* __restrict__ ext_in, int in_buf, int out_buf,
    const float* __restrict__ epsv, int layer,
    const float* __restrict__ W1, const float* __restrict__ b1,
    const float* __restrict__ W2, const float* __restrict__ b2,
    float* __restrict__ dout)
{
    constexpr int R4   = DIN / 4;          // float4 per row (4 or 8)
    constexpr int SH   = (DIN == 16) ? 2 : 3;  // log2(R4)
    constexpr int RINC = 32 >> SH;         // row increment per m (8 or 4)
    constexpr int V4   = NMAX * R4;        // float4 per node block (256/512)
    constexpr int MV   = V4 / 32;          // float4 slots per lane (8/16)
    constexpr int PAD  = 36;               // row stride (floats); 144B = 16B-aligned

    __shared__ float sW1[DIN * 32];
    __shared__ float sW2[32 * 32];
    __shared__ float sb1[32], sb2[32];
    extern __shared__ float sxh_dyn[];     // 8 x 64 x PAD floats

    int tid = threadIdx.x;
    int wid = tid >> 5, lane = tid & 31;
    int lr = lane >> 2, q = lane & 3;

    for (int i = tid; i < DIN * 32; i += 256) sW1[i] = W1[i];
    for (int i = tid; i < 32 * 32;  i += 256) sW2[i] = W2[i];
    if (tid < 32) { sb1[tid] = b1[tid]; sb2[tid] = b2[tid]; }
    float ep1 = 1.0f + epsv[layer];
    __syncthreads();

    const float*  h_in = ext_in ? ext_in : g_h[in_buf];
    const float4* h4   = (const float4*)h_in;
    float* sxw = sxh_dyn + wid * (64 * PAD);

    // staging coordinates for lane's slot set (slot = m*32 + lane)
    const int stg_colf = (lane & (R4 - 1)) * 4;     // float column
    const int stg_row0 = lane >> SH;                // row for m=0

    for (int n = blockIdx.x * 8 + wid; n < NSUM; n += gridDim.x * 8) {
        // ---- gather: acc = (1+eps)*h[n] + sum_neighbors h[src] ----
        float4 acc[MV];
        {
            const float4* hn = h4 + (size_t)n * V4 + lane;
            #pragma unroll
            for (int m = 0; m < MV; m++) {
                float4 t = hn[m * 32];
                acc[m] = make_float4(ep1 * t.x, ep1 * t.y, ep1 * t.z, ep1 * t.w);
            }
        }
        int e0 = g_off[n], e1 = g_off[n + 1];
        for (int base = e0; base < e1; base += 32) {
            int cnt = min(32, e1 - base);
            int id = (lane < cnt) ? g_esrc[base + lane] : 0;
            int e = 0;
            if (DIN == 16) {
                // 2-edge-wide register-buffered gather
                for (; e + 2 <= cnt; e += 2) {
                    int sa = __shfl_sync(0xffffffffu, id, e);
                    int sb = __shfl_sync(0xffffffffu, id, e + 1);
                    const float4* pa = h4 + (size_t)sa * V4 + lane;
                    const float4* pb = h4 + (size_t)sb * V4 + lane;
                    float4 ta[MV], tb[MV];
                    #pragma unroll
                    for (int m = 0; m < MV; m++) ta[m] = pa[m * 32];
                    #pragma unroll
                    for (int m = 0; m < MV; m++) tb[m] = pb[m * 32];
                    #pragma unroll
                    for (int m = 0; m < MV; m++) {
                        acc[m].x += ta[m].x; acc[m].y += ta[m].y;
                        acc[m].z += ta[m].z; acc[m].w += ta[m].w;
                    }
                    #pragma unroll
                    for (int m = 0; m < MV; m++) {
                        acc[m].x += tb[m].x; acc[m].y += tb[m].y;
                        acc[m].z += tb[m].z; acc[m].w += tb[m].w;
                    }
                }
                if (e < cnt) {
                    int sa = __shfl_sync(0xffffffffu, id, e);
                    const float4* pa = h4 + (size_t)sa * V4 + lane;
                    #pragma unroll
                    for (int m = 0; m < MV; m++) {
                        float4 t = pa[m * 32];
                        acc[m].x += t.x; acc[m].y += t.y;
                        acc[m].z += t.z; acc[m].w += t.w;
                    }
                }
            } else {
                // pointer-pipelined gather (next address precomputed)
                int sa0 = __shfl_sync(0xffffffffu, id, 0);
                const float4* pa = h4 + (size_t)sa0 * V4 + lane;
                for (; e < cnt; e++) {
                    int enext = (e + 1 < cnt) ? e + 1 : e;
                    int sn = __shfl_sync(0xffffffffu, id, enext);
                    const float4* pnext = h4 + (size_t)sn * V4 + lane;
                    #pragma unroll
                    for (int m = 0; m < MV; m++) {
                        float4 t = pa[m * 32];
                        acc[m].x += t.x; acc[m].y += t.y;
                        acc[m].z += t.z; acc[m].w += t.w;
                    }
                    pa = pnext;
                }
            }
        }
        // stage x into this warp's smem slice at (row, col) of each slot
        #pragma unroll
        for (int m = 0; m < MV; m++) {
            int row = stg_row0 + m * RINC;
            float* p = &sxw[row * PAD + stg_colf];
            *(float4*)p = acc[m];
        }
        __syncwarp();

        // ---- hidden: hid = relu(x @ W1 + b1); lane: 8 rows x 4 col-pairs ----
        unsigned long long h2[32];
        {
            float4 bb0 = *(const float4*)&sb1[q * 8];
            float4 bb1 = *(const float4*)&sb1[q * 8 + 4];
            unsigned long long bp[4] = {pack2(bb0.x, bb0.y), pack2(bb0.z, bb0.w),
                                        pack2(bb1.x, bb1.y), pack2(bb1.z, bb1.w)};
            #pragma unroll
            for (int m = 0; m < 8; m++)
                #pragma unroll
                for (int p = 0; p < 4; p++) h2[m * 4 + p] = bp[p];
        }
        #pragma unroll
        for (int kb = 0; kb < DIN / 4; kb++) {
            float4 xq[8];
            #pragma unroll
            for (int m = 0; m < 8; m++)
                xq[m] = *(const float4*)&sxw[(lr + 8 * m) * PAD + kb * 4];
            #pragma unroll
            for (int kk = 0; kk < 4; kk++) {
                int k = kb * 4 + kk;
                float4 w0 = *(const float4*)&sW1[k * 32 + q * 8];
                float4 w1 = *(const float4*)&sW1[k * 32 + q * 8 + 4];
                unsigned long long wp[4] = {pack2(w0.x, w0.y), pack2(w0.z, w0.w),
                                            pack2(w1.x, w1.y), pack2(w1.z, w1.w)};
                #pragma unroll
                for (int m = 0; m < 8; m++) {
                    float xv = (kk == 0) ? xq[m].x : (kk == 1) ? xq[m].y
                             : (kk == 2) ? xq[m].z : xq[m].w;
                    unsigned long long xa = pack2dup(xv);
                    #pragma unroll
                    for (int p = 0; p < 4; p++)
                        fma2(h2[m * 4 + p], xa, wp[p]);
                }
            }
        }
        __syncwarp();   // all x reads done before hid overwrites the buffer
        #pragma unroll
        for (int m = 0; m < 8; m++) {
            float2 p0 = unpack2(h2[m * 4 + 0]);
            float2 p1 = unpack2(h2[m * 4 + 1]);
            float2 p2 = unpack2(h2[m * 4 + 2]);
            float2 p3 = unpack2(h2[m * 4 + 3]);
            float* p = &sxw[(lr + 8 * m) * PAD + q * 8];
            ((float4*)p)[0] = make_float4(fmaxf(p0.x, 0.f), fmaxf(p0.y, 0.f),
                                          fmaxf(p1.x, 0.f), fmaxf(p1.y, 0.f));
            ((float4*)p)[1] = make_float4(fmaxf(p2.x, 0.f), fmaxf(p2.y, 0.f),
                                          fmaxf(p3.x, 0.f), fmaxf(p3.y, 0.f));
        }
        __syncwarp();

        // ---- output: out = hid @ W2 + b2 ----
        unsigned long long o2[32];
        {
            float4 bb0 = *(const float4*)&sb2[q * 8];
            float4 bb1 = *(const float4*)&sb2[q * 8 + 4];
            unsigned long long bp[4] = {pack2(bb0.x, bb0.y), pack2(bb0.z, bb0.w),
                                        pack2(bb1.x, bb1.y), pack2(bb1.z, bb1.w)};
            #pragma unroll
            for (int m = 0; m < 8; m++)
                #pragma unroll
                for (int p = 0; p < 4; p++) o2[m * 4 + p] = bp[p];
        }
        #pragma unroll
        for (int jb = 0; jb < 8; jb++) {
            float4 hq[8];
            #pragma unroll
            for (int m = 0; m < 8; m++)
                hq[m] = *(const float4*)&sxw[(lr + 8 * m) * PAD + jb * 4];
            #pragma unroll
            for (int jj = 0; jj < 4; jj++) {
                int j = jb * 4 + jj;
                float4 w0 = *(const float4*)&sW2[j * 32 + q * 8];
                float4 w1 = *(const float4*)&sW2[j * 32 + q * 8 + 4];
                unsigned long long wp[4] = {pack2(w0.x, w0.y), pack2(w0.z, w0.w),
                                            pack2(w1.x, w1.y), pack2(w1.z, w1.w)};
                #pragma unroll
                for (int m = 0; m < 8; m++) {
                    float hv = (jj == 0) ? hq[m].x : (jj == 1) ? hq[m].y
                             : (jj == 2) ? hq[m].z : hq[m].w;
                    unsigned long long ha = pack2dup(hv);
                    #pragma unroll
                    for (int p = 0; p < 4; p++)
                        fma2(o2[m * 4 + p], ha, wp[p]);
                }
            }
        }
        __syncwarp();   // hid reads done before next iteration stages x

        if (!POOL) {
            #pragma unroll
            for (int m = 0; m < 8; m++) {
                float2 p0 = unpack2(o2[m * 4 + 0]);
                float2 p1 = unpack2(o2[m * 4 + 1]);
                float2 p2 = unpack2(o2[m * 4 + 2]);
                float2 p3 = unpack2(o2[m * 4 + 3]);
                float4 v0 = make_float4(p0.x, p0.y, p1.x, p1.y);
                float4 v1 = make_float4(p2.x, p2.y, p3.x, p3.y);
                if (RELU_OUT) {
                    v0.x = fmaxf(v0.x, 0.f); v0.y = fmaxf(v0.y, 0.f);
                    v0.z = fmaxf(v0.z, 0.f); v0.w = fmaxf(v0.w, 0.f);
                    v1.x = fmaxf(v1.x, 0.f); v1.y = fmaxf(v1.y, 0.f);
                    v1.z = fmaxf(v1.z, 0.f); v1.w = fmaxf(v1.w, 0.f);
                }
                int grow = lr + 8 * m;
                float* out = g_h[out_buf] + (size_t)n * (NMAX * 32) + grow * 32 + q * 8;
                ((float4*)out)[0] = v0;
                ((float4*)out)[1] = v1;
            }
        } else {
            // sum over lane's 8 rows, then over lr (lane bits 2..4) -> all 64
            float o[8];
            #pragma unroll
            for (int i = 0; i < 8; i++) o[i] = 0.0f;
            #pragma unroll
            for (int m = 0; m < 8; m++) {
                float2 p0 = unpack2(o2[m * 4 + 0]);
                float2 p1 = unpack2(o2[m * 4 + 1]);
                float2 p2 = unpack2(o2[m * 4 + 2]);
                float2 p3 = unpack2(o2[m * 4 + 3]);
                o[0] += p0.x; o[1] += p0.y; o[2] += p1.x; o[3] += p1.y;
                o[4] += p2.x; o[5] += p2.y; o[6] += p3.x; o[7] += p3.y;
            }
            #pragma unroll
            for (int s = 4; s <= 16; s <<= 1) {
                #pragma unroll
                for (int i = 0; i < 8; i++)
                    o[i] += __shfl_xor_sync(0xffffffffu, o[i], s);
            }
            if (lane < 4) {
                float* p = &dout[n * 32 + q * 8];
                ((float4*)p)[0] = make_float4(o[0], o[1], o[2], o[3]);
                ((float4*)p)[1] = make_float4(o[4], o[5], o[6], o[7]);
            }
        }
    }
}

// ---------------------------------------------------------------------------
extern "C" void kernel_launch(void* const* d_in, const int* in_sizes, int n_in,
                              void* d_out, int out_size)
{
    const float* W    = (const float*)d_in[0];   // [6400, 64, 16]
    const int*   ei   = (const int*)d_in[1];     // [2, E] row-major
    const float* eps  = (const float*)d_in[2];   // [3]
    const float* W1_0 = (const float*)d_in[3];
    const float* b1_0 = (const float*)d_in[4];
    const float* W2_0 = (const float*)d_in[5];
    const float* b2_0 = (const float*)d_in[6];
    const float* W1_1 = (const float*)d_in[7];
    const float* b1_1 = (const float*)d_in[8];
    const float* W2_1 = (const float*)d_in[9];
    const float* b2_1 = (const float*)d_in[10];
    const float* W1_2 = (const float*)d_in[11];
    const float* b1_2 = (const float*)d_in[12];
    const float* W2_2 = (const float*)d_in[13];
    const float* b2_2 = (const float*)d_in[14];
    float* out = (float*)d_out;

    const int* src = ei;
    const int* dst = ei + EDGES;

    const int DYN = 8 * 64 * 36 * (int)sizeof(float);   // 73728 B
    cudaFuncSetAttribute(k_layer<16, true, false>,
                         cudaFuncAttributeMaxDynamicSharedMemorySize, DYN);
    cudaFuncSetAttribute(k_layer<32, true, false>,
                         cudaFuncAttributeMaxDynamicSharedMemorySize, DYN);
    cudaFuncSetAttribute(k_layer<32, false, true>,
                         cudaFuncAttributeMaxDynamicSharedMemorySize, DYN);

    // CSR build (g_cnt is zero at load and re-zeroed by k_scan each call)
    k_count<<<(EDGES + 255) / 256, 256>>>(dst);          // launch 0
    k_scan<<<1, 1024>>>();                                // launch 1
    k_scatter<<<(EDGES + 255) / 256, 256>>>(src, dst);   // launch 2

    const int GRID = 296;   // one persistent wave: 2 blocks x 148 SMs

    // Layer 0: input W (D=16) -> g_h[0]  (relu after MLP)   -- launch 3
    k_layer<16, true, false><<<GRID, 256, DYN>>>(W, 0, 0, eps, 0,
                                                 W1_0, b1_0, W2_0, b2_0, nullptr);
    // Layer 1: g_h[0] -> g_h[1]  (relu after MLP)           -- launch 4
    k_layer<32, true, false><<<GRID, 256, DYN>>>(nullptr, 0, 1, eps, 1,
                                                 W1_1, b1_1, W2_1, b2_1, nullptr);
    // Layer 2: g_h[1] -> pooled d_out directly (no relu)    -- launch 5
    k_layer<32, false, true><<<GRID, 256, DYN>>>(nullptr, 1, 0, eps, 2,
                                                 W1_2, b1_2, W2_2, b2_2, out);
}

// round 15
// speedup vs baseline: 1.3037x; 1.1173x over previous
#include <cuda_runtime.h>
#include <cuda_fp16.h>

// Problem constants (fixed shapes per reference)
#define NSUM 6400
#define NMAX 64
#define MDIM 16
#define HDIM 32
#define ODIM 32
#define EDGES 51200

// Scratch: ping/pong node-feature buffers (fp16, uint4-aligned) + CSR.
// Each buffer: NSUM nodes x 64 rows x 32 cols fp16 = 256 uint4/node = 26.2MB.
__device__ uint4 g_hh[2][NSUM * 256];
__device__ int g_cnt[NSUM];                    // zero-init at load; k_scan re-zeroes
__device__ int g_off[NSUM + 1];
__device__ int g_cur[NSUM];
__device__ int g_esrc[EDGES];

// ---- packed fp32x2 helpers (Blackwell dual-FMA; full fp32 precision) ----
__device__ __forceinline__ unsigned long long pack2(float lo, float hi) {
    unsigned long long r;
    asm("mov.b64 %0, {%1, %2};" : "=l"(r) : "f"(lo), "f"(hi));
    return r;
}
__device__ __forceinline__ unsigned long long pack2dup(float v) {
    unsigned long long r;
    asm("mov.b64 %0, {%1, %1};" : "=l"(r) : "f"(v));
    return r;
}
__device__ __forceinline__ void fma2(unsigned long long& d,
                                     unsigned long long a, unsigned long long b) {
    asm("fma.rn.f32x2 %0, %1, %2, %0;" : "+l"(d) : "l"(a), "l"(b));
}
__device__ __forceinline__ float2 unpack2(unsigned long long v) {
    float lo, hi;
    asm("mov.b64 {%0, %1}, %2;" : "=f"(lo), "=f"(hi) : "l"(v));
    return make_float2(lo, hi);
}

// ---- fp16 pack/unpack (storage only; all math stays fp32) ----
__device__ __forceinline__ float2 h2f(unsigned int w) {
    __half2 h = *reinterpret_cast<__half2*>(&w);
    return __half22float2(h);
}
__device__ __forceinline__ unsigned int f2h(float a, float b) {
    __half2 h = __floats2half2_rn(a, b);
    return *reinterpret_cast<unsigned int*>(&h);
}

// ---------------------------------------------------------------------------
// CSR build: count -> scan (self-cleaning) -> scatter
// ---------------------------------------------------------------------------
__global__ void k_count(const int* __restrict__ dst) {
    int e = blockIdx.x * blockDim.x + threadIdx.x;
    if (e < EDGES) atomicAdd(&g_cnt[dst[e]], 1);
}

__global__ void k_scan() {
    __shared__ int part[1024];
    int tid = threadIdx.x;
    const int CH = (NSUM + 1023) / 1024;  // 7
    int base = tid * CH;
    int s = 0;
    #pragma unroll
    for (int i = 0; i < CH; i++) {
        int idx = base + i;
        if (idx < NSUM) s += g_cnt[idx];
    }
    part[tid] = s;
    __syncthreads();
    int own = s;
    for (int d = 1; d < 1024; d <<= 1) {
        int v = (tid >= d) ? part[tid - d] : 0;
        __syncthreads();
        part[tid] += v;
        __syncthreads();
    }
    int run = part[tid] - own;
    #pragma unroll
    for (int i = 0; i < CH; i++) {
        int idx = base + i;
        if (idx < NSUM) {
            g_off[idx] = run;
            g_cur[idx] = run;
            run += g_cnt[idx];
            g_cnt[idx] = 0;          // self-clean for the next replay
        }
    }
    if (tid == 1023) g_off[NSUM] = EDGES;
}

__global__ void k_scatter(const int* __restrict__ src, const int* __restrict__ dst) {
    int e = blockIdx.x * blockDim.x + threadIdx.x;
    if (e < EDGES) {
        int p = atomicAdd(&g_cur[dst[e]], 1);
        g_esrc[p] = src[e];
    }
}

// ---------------------------------------------------------------------------
// Warp-per-NODE fused GIN layer (64 rows per warp).
// IN_HALF=false (layer 0): fp32 external input, D=16, linear float4 gather
//   (identical to the validated R14 path).
// IN_HALF=true  (layers 1/2): fp16 h buffer, D=32. Lane loads 8 contiguous
//   uint4 (512B warp blocks, 4 wavefronts) per edge -> HALF the loads,
//   wavefronts, bytes and latency footprint of the fp32 version.
//   Conversion to fp32 on load; accumulation fully fp32.
// MLP: fp32 in shared, f32x2 dual-FMA (unchanged). Non-POOL output stored
// as fp16 (round-to-nearest). POOL reduces in-warp, writes fp32 dout.
// Dynamic smem: 8 warps x 64 x 36 floats (x/hid union).
// ---------------------------------------------------------------------------
template <int DIN, bool IN_HALF, bool RELU_OUT, bool POOL>
__global__ __launch_bounds__(256, 2) void k_layer(
    const float* __restrict__ ext_in, int in_buf, int out_buf,
    const float* __restrict__ epsv, int layer,
    const float* __restrict__ W1, const float* __restrict__ b1,
    const float* __restrict__ W2, const float* __restrict__ b2,
    float* __restrict__ dout)
{
    constexpr int PAD  = 36;               // smem row stride (floats)

    __shared__ float sW1[DIN * 32];
    __shared__ float sW2[32 * 32];
    __shared__ float sb1[32], sb2[32];
    extern __shared__ float sxh_dyn[];     // 8 x 64 x PAD floats

    int tid = threadIdx.x;
    int wid = tid >> 5, lane = tid & 31;
    int lr = lane >> 2, q = lane & 3;

    for (int i = tid; i < DIN * 32; i += 256) sW1[i] = W1[i];
    for (int i = tid; i < 32 * 32;  i += 256) sW2[i] = W2[i];
    if (tid < 32) { sb1[tid] = b1[tid]; sb2[tid] = b2[tid]; }
    float ep1 = 1.0f + epsv[layer];
    __syncthreads();

    float* sxw = sxh_dyn + wid * (64 * PAD);

    for (int n = blockIdx.x * 8 + wid; n < NSUM; n += gridDim.x * 8) {
        int e0 = g_off[n], e1 = g_off[n + 1];

        if constexpr (!IN_HALF) {
            // ---- fp32 gather, D=16 (layer 0) — validated R14 path ----
            constexpr int R4 = DIN / 4;        // 4
            constexpr int V4 = NMAX * R4;      // 256
            constexpr int MV = V4 / 32;        // 8
            const float4* h4 = (const float4*)ext_in;

            float4 acc[MV];
            {
                const float4* hn = h4 + (size_t)n * V4 + lane;
                #pragma unroll
                for (int m = 0; m < MV; m++) {
                    float4 t = hn[m * 32];
                    acc[m] = make_float4(ep1 * t.x, ep1 * t.y, ep1 * t.z, ep1 * t.w);
                }
            }
            for (int base = e0; base < e1; base += 32) {
                int cnt = min(32, e1 - base);
                int id = (lane < cnt) ? g_esrc[base + lane] : 0;
                int e = 0;
                for (; e + 2 <= cnt; e += 2) {
                    int sa = __shfl_sync(0xffffffffu, id, e);
                    int sb = __shfl_sync(0xffffffffu, id, e + 1);
                    const float4* pa = h4 + (size_t)sa * V4 + lane;
                    const float4* pb = h4 + (size_t)sb * V4 + lane;
                    float4 ta[MV], tb[MV];
                    #pragma unroll
                    for (int m = 0; m < MV; m++) ta[m] = pa[m * 32];
                    #pragma unroll
                    for (int m = 0; m < MV; m++) tb[m] = pb[m * 32];
                    #pragma unroll
                    for (int m = 0; m < MV; m++) {
                        acc[m].x += ta[m].x; acc[m].y += ta[m].y;
                        acc[m].z += ta[m].z; acc[m].w += ta[m].w;
                    }
                    #pragma unroll
                    for (int m = 0; m < MV; m++) {
                        acc[m].x += tb[m].x; acc[m].y += tb[m].y;
                        acc[m].z += tb[m].z; acc[m].w += tb[m].w;
                    }
                }
                if (e < cnt) {
                    int sa = __shfl_sync(0xffffffffu, id, e);
                    const float4* pa = h4 + (size_t)sa * V4 + lane;
                    #pragma unroll
                    for (int m = 0; m < MV; m++) {
                        float4 t = pa[m * 32];
                        acc[m].x += t.x; acc[m].y += t.y;
                        acc[m].z += t.z; acc[m].w += t.w;
                    }
                }
            }
            // stage: slot = m*32+lane; row = slot>>2, colf = (slot&3)*4; RINC=8
            #pragma unroll
            for (int m = 0; m < MV; m++) {
                int row = (lane >> 2) + m * 8;
                float* p = &sxw[row * PAD + (lane & 3) * 4];
                *(float4*)p = acc[m];
            }
        } else {
            // ---- fp16 gather, D=32 (layers 1/2) ----
            // node block = 256 uint4; lane owns slots {m*32+lane, m=0..7}
            // slot -> row = slot>>2, half-col = (slot&3)*8
            const uint4* hb = g_hh[in_buf];
            float accf[64];
            {
                const uint4* hn = hb + (size_t)n * 256 + lane;
                #pragma unroll
                for (int m = 0; m < 8; m++) {
                    uint4 t = hn[m * 32];
                    float2 f0 = h2f(t.x), f1 = h2f(t.y), f2 = h2f(t.z), f3 = h2f(t.w);
                    accf[m*8+0] = ep1 * f0.x; accf[m*8+1] = ep1 * f0.y;
                    accf[m*8+2] = ep1 * f1.x; accf[m*8+3] = ep1 * f1.y;
                    accf[m*8+4] = ep1 * f2.x; accf[m*8+5] = ep1 * f2.y;
                    accf[m*8+6] = ep1 * f3.x; accf[m*8+7] = ep1 * f3.y;
                }
            }
            for (int base = e0; base < e1; base += 32) {
                int cnt = min(32, e1 - base);
                int id = (lane < cnt) ? g_esrc[base + lane] : 0;
                int sa0 = __shfl_sync(0xffffffffu, id, 0);
                const uint4* pa = hb + (size_t)sa0 * 256 + lane;
                for (int e = 0; e < cnt; e++) {
                    int en = (e + 1 < cnt) ? e + 1 : e;
                    int sn = __shfl_sync(0xffffffffu, id, en);
                    const uint4* pn = hb + (size_t)sn * 256 + lane;
                    #pragma unroll
                    for (int m = 0; m < 8; m++) {
                        uint4 t = pa[m * 32];
                        float2 f0 = h2f(t.x), f1 = h2f(t.y);
                        float2 f2 = h2f(t.z), f3 = h2f(t.w);
                        accf[m*8+0] += f0.x; accf[m*8+1] += f0.y;
                        accf[m*8+2] += f1.x; accf[m*8+3] += f1.y;
                        accf[m*8+4] += f2.x; accf[m*8+5] += f2.y;
                        accf[m*8+6] += f3.x; accf[m*8+7] += f3.y;
                    }
                    pa = pn;
                }
            }
            // stage: row = m*8 + (lane>>2), col floats = (lane&3)*8
            #pragma unroll
            for (int m = 0; m < 8; m++) {
                float* p = &sxw[(m * 8 + lr) * PAD + q * 8];
                ((float4*)p)[0] = make_float4(accf[m*8+0], accf[m*8+1],
                                              accf[m*8+2], accf[m*8+3]);
                ((float4*)p)[1] = make_float4(accf[m*8+4], accf[m*8+5],
                                              accf[m*8+6], accf[m*8+7]);
            }
        }
        __syncwarp();

        // ---- hidden: hid = relu(x @ W1 + b1); lane: 8 rows x 4 col-pairs ----
        unsigned long long h2v[32];
        {
            float4 bb0 = *(const float4*)&sb1[q * 8];
            float4 bb1 = *(const float4*)&sb1[q * 8 + 4];
            unsigned long long bp[4] = {pack2(bb0.x, bb0.y), pack2(bb0.z, bb0.w),
                                        pack2(bb1.x, bb1.y), pack2(bb1.z, bb1.w)};
            #pragma unroll
            for (int m = 0; m < 8; m++)
                #pragma unroll
                for (int p = 0; p < 4; p++) h2v[m * 4 + p] = bp[p];
        }
        #pragma unroll
        for (int kb = 0; kb < DIN / 4; kb++) {
            float4 xq[8];
            #pragma unroll
            for (int m = 0; m < 8; m++)
                xq[m] = *(const float4*)&sxw[(lr + 8 * m) * PAD + kb * 4];
            #pragma unroll
            for (int kk = 0; kk < 4; kk++) {
                int k = kb * 4 + kk;
                float4 w0 = *(const float4*)&sW1[k * 32 + q * 8];
                float4 w1 = *(const float4*)&sW1[k * 32 + q * 8 + 4];
                unsigned long long wp[4] = {pack2(w0.x, w0.y), pack2(w0.z, w0.w),
                                            pack2(w1.x, w1.y), pack2(w1.z, w1.w)};
                #pragma unroll
                for (int m = 0; m < 8; m++) {
                    float xv = (kk == 0) ? xq[m].x : (kk == 1) ? xq[m].y
                             : (kk == 2) ? xq[m].z : xq[m].w;
                    unsigned long long xa = pack2dup(xv);
                    #pragma unroll
                    for (int p = 0; p < 4; p++)
                        fma2(h2v[m * 4 + p], xa, wp[p]);
                }
            }
        }
        __syncwarp();   // all x reads done before hid overwrites the buffer
        #pragma unroll
        for (int m = 0; m < 8; m++) {
            float2 p0 = unpack2(h2v[m * 4 + 0]);
            float2 p1 = unpack2(h2v[m * 4 + 1]);
            float2 p2 = unpack2(h2v[m * 4 + 2]);
            float2 p3 = unpack2(h2v[m * 4 + 3]);
            float* p = &sxw[(lr + 8 * m) * PAD + q * 8];
            ((float4*)p)[0] = make_float4(fmaxf(p0.x, 0.f), fmaxf(p0.y, 0.f),
                                          fmaxf(p1.x, 0.f), fmaxf(p1.y, 0.f));
            ((float4*)p)[1] = make_float4(fmaxf(p2.x, 0.f), fmaxf(p2.y, 0.f),
                                          fmaxf(p3.x, 0.f), fmaxf(p3.y, 0.f));
        }
        __syncwarp();

        // ---- output: out = hid @ W2 + b2 ----
        unsigned long long o2[32];
        {
            float4 bb0 = *(const float4*)&sb2[q * 8];
            float4 bb1 = *(const float4*)&sb2[q * 8 + 4];
            unsigned long long bp[4] = {pack2(bb0.x, bb0.y), pack2(bb0.z, bb0.w),
                                        pack2(bb1.x, bb1.y), pack2(bb1.z, bb1.w)};
            #pragma unroll
            for (int m = 0; m < 8; m++)
                #pragma unroll
                for (int p = 0; p < 4; p++) o2[m * 4 + p] = bp[p];
        }
        #pragma unroll
        for (int jb = 0; jb < 8; jb++) {
            float4 hq[8];
            #pragma unroll
            for (int m = 0; m < 8; m++)
                hq[m] = *(const float4*)&sxw[(lr + 8 * m) * PAD + jb * 4];
            #pragma unroll
            for (int jj = 0; jj < 4; jj++) {
                int j = jb * 4 + jj;
                float4 w0 = *(const float4*)&sW2[j * 32 + q * 8];
                float4 w1 = *(const float4*)&sW2[j * 32 + q * 8 + 4];
                unsigned long long wp[4] = {pack2(w0.x, w0.y), pack2(w0.z, w0.w),
                                            pack2(w1.x, w1.y), pack2(w1.z, w1.w)};
                #pragma unroll
                for (int m = 0; m < 8; m++) {
                    float hv = (jj == 0) ? hq[m].x : (jj == 1) ? hq[m].y
                             : (jj == 2) ? hq[m].z : hq[m].w;
                    unsigned long long ha = pack2dup(hv);
                    #pragma unroll
                    for (int p = 0; p < 4; p++)
                        fma2(o2[m * 4 + p], ha, wp[p]);
                }
            }
        }
        __syncwarp();   // hid reads done before next iteration stages x

        if (!POOL) {
            // store fp16: row = lr+8m, 8 half cols at q*8 -> one uint4
            uint4* ob = g_hh[out_buf] + (size_t)n * 256;
            #pragma unroll
            for (int m = 0; m < 8; m++) {
                float2 p0 = unpack2(o2[m * 4 + 0]);
                float2 p1 = unpack2(o2[m * 4 + 1]);
                float2 p2 = unpack2(o2[m * 4 + 2]);
                float2 p3 = unpack2(o2[m * 4 + 3]);
                float v[8] = {p0.x, p0.y, p1.x, p1.y, p2.x, p2.y, p3.x, p3.y};
                if (RELU_OUT) {
                    #pragma unroll
                    for (int i = 0; i < 8; i++) v[i] = fmaxf(v[i], 0.0f);
                }
                uint4 o;
                o.x = f2h(v[0], v[1]); o.y = f2h(v[2], v[3]);
                o.z = f2h(v[4], v[5]); o.w = f2h(v[6], v[7]);
                int grow = lr + 8 * m;
                ob[grow * 4 + q] = o;
            }
        } else {
            // sum over lane's 8 rows, then over lr (lane bits 2..4) -> all 64
            float o[8];
            #pragma unroll
            for (int i = 0; i < 8; i++) o[i] = 0.0f;
            #pragma unroll
            for (int m = 0; m < 8; m++) {
                float2 p0 = unpack2(o2[m * 4 + 0]);
                float2 p1 = unpack2(o2[m * 4 + 1]);
                float2 p2 = unpack2(o2[m * 4 + 2]);
                float2 p3 = unpack2(o2[m * 4 + 3]);
                o[0] += p0.x; o[1] += p0.y; o[2] += p1.x; o[3] += p1.y;
                o[4] += p2.x; o[5] += p2.y; o[6] += p3.x; o[7] += p3.y;
            }
            #pragma unroll
            for (int s = 4; s <= 16; s <<= 1) {
                #pragma unroll
                for (int i = 0; i < 8; i++)
                    o[i] += __shfl_xor_sync(0xffffffffu, o[i], s);
            }
            if (lane < 4) {
                float* p = &dout[n * 32 + q * 8];
                ((float4*)p)[0] = make_float4(o[0], o[1], o[2], o[3]);
                ((float4*)p)[1] = make_float4(o[4], o[5], o[6], o[7]);
            }
        }
    }
}

// ---------------------------------------------------------------------------
extern "C" void kernel_launch(void* const* d_in, const int* in_sizes, int n_in,
                              void* d_out, int out_size)
{
    const float* W    = (const float*)d_in[0];   // [6400, 64, 16]
    const int*   ei   = (const int*)d_in[1];     // [2, E] row-major
    const float* eps  = (const float*)d_in[2];   // [3]
    const float* W1_0 = (const float*)d_in[3];
    const float* b1_0 = (const float*)d_in[4];
    const float* W2_0 = (const float*)d_in[5];
    const float* b2_0 = (const float*)d_in[6];
    const float* W1_1 = (const float*)d_in[7];
    const float* b1_1 = (const float*)d_in[8];
    const float* W2_1 = (const float*)d_in[9];
    const float* b2_1 = (const float*)d_in[10];
    const float* W1_2 = (const float*)d_in[11];
    const float* b1_2 = (const float*)d_in[12];
    const float* W2_2 = (const float*)d_in[13];
    const float* b2_2 = (const float*)d_in[14];
    float* out = (float*)d_out;

    const int* src = ei;
    const int* dst = ei + EDGES;

    const int DYN = 8 * 64 * 36 * (int)sizeof(float);   // 73728 B
    cudaFuncSetAttribute(k_layer<16, false, true, false>,
                         cudaFuncAttributeMaxDynamicSharedMemorySize, DYN);
    cudaFuncSetAttribute(k_layer<32, true, true, false>,
                         cudaFuncAttributeMaxDynamicSharedMemorySize, DYN);
    cudaFuncSetAttribute(k_layer<32, true, false, true>,
                         cudaFuncAttributeMaxDynamicSharedMemorySize, DYN);

    // CSR build (g_cnt is zero at load and re-zeroed by k_scan each call)
    k_count<<<(EDGES + 255) / 256, 256>>>(dst);          // launch 0
    k_scan<<<1, 1024>>>();                                // launch 1
    k_scatter<<<(EDGES + 255) / 256, 256>>>(src, dst);   // launch 2

    const int GRID = 296;   // one persistent wave: 2 blocks x 148 SMs

    // Layer 0: input W fp32 (D=16) -> g_hh[0] fp16 (relu)   -- launch 3
    k_layer<16, false, true, false><<<GRID, 256, DYN>>>(W, 0, 0, eps, 0,
                                                        W1_0, b1_0, W2_0, b2_0, nullptr);
    // Layer 1: g_hh[0] -> g_hh[1] fp16 (relu)               -- launch 4
    k_layer<32, true, true, false><<<GRID, 256, DYN>>>(nullptr, 0, 1, eps, 1,
                                                       W1_1, b1_1, W2_1, b2_1, nullptr);
    // Layer 2: g_hh[1] -> pooled fp32 d_out (no relu)       -- launch 5
    k_layer<32, true, false, true><<<GRID, 256, DYN>>>(nullptr, 1, 0, eps, 2,
                                                       W1_2, b1_2, W2_2, b2_2, out);
}